// round 2
// baseline (speedup 1.0000x reference)
#include <cuda_runtime.h>
#include <cstddef>

// Problem constants
#define NB    32      // batch
#define NN    512     // nodes
#define DIN_  64
#define DOUT_ 64
#define ET_   32
#define CHEB  3
#define KI_   (CHEB * DIN_)   // 192

// Scratch: h[b][k][n][i]  (32*3*512*64 floats = 12.6 MB)
__device__ float g_h[(size_t)NB * CHEB * NN * DIN_];

// ---------------------------------------------------------------------------
// Kernel 1/2: C[512x64] = A[512x512] @ Bm[512x64]   (per batch)
// MODE 0: blockIdx.z selects A=SC (->h0) or A=R (->h1), Bm = x
// MODE 1: A=R, Bm=h1, C = 2*acc - h0  (->h2)
// Tile: BM=128 rows x 64 cols, BK=16, 256 threads, 8x4 micro-tile per thread.
// ---------------------------------------------------------------------------
template<int MODE>
__global__ __launch_bounds__(256) void prop_gemm(
    const float* __restrict__ R,
    const float* __restrict__ SC,
    const float* __restrict__ X)
{
    constexpr int BM = 128, BK = 16;
    __shared__ float AsT[BK][BM + 4];   // transposed A tile, stride 132 (16B-aligned rows)
    __shared__ float Bs[BK][64];

    const int b = blockIdx.y;
    const int rowBlk = blockIdx.x * BM;

    float* hb = g_h + (size_t)b * (CHEB * NN * DIN_);
    const float* A;
    const float* Bm;
    const float* Sub = nullptr;
    float* C;
    if (MODE == 0) {
        const int which = blockIdx.z;             // 0 -> SC, 1 -> R
        A  = (which == 0 ? SC : R) + (size_t)b * NN * NN;
        Bm = X + (size_t)b * NN * DIN_;
        C  = hb + (size_t)which * NN * DIN_;
    } else {
        A   = R  + (size_t)b * NN * NN;
        Bm  = hb + (size_t)1 * NN * DIN_;         // h1
        Sub = hb + (size_t)0 * NN * DIN_;         // h0
        C   = hb + (size_t)2 * NN * DIN_;         // h2
    }

    const int t  = threadIdx.x;
    const int tx = t & 15;        // column group (0..15)
    const int ty = t >> 4;        // row group    (0..15)
    const int colBase = tx * 4;
    const int rBase   = ty * 8;

    float acc[8][4];
    #pragma unroll
    for (int i = 0; i < 8; ++i)
        #pragma unroll
        for (int j = 0; j < 4; ++j) acc[i][j] = 0.f;

    for (int k0 = 0; k0 < NN; k0 += BK) {
        // Load A tile [128 rows][16 k], store transposed. 512 float4, 2/thread.
        #pragma unroll
        for (int it = 0; it < 2; ++it) {
            const int idx = t + it * 256;          // 0..511
            const int row = idx >> 2;              // 0..127
            const int kq  = (idx & 3) * 4;         // 0,4,8,12
            const float4 v = *reinterpret_cast<const float4*>(
                A + (size_t)(rowBlk + row) * NN + k0 + kq);
            AsT[kq + 0][row] = v.x;
            AsT[kq + 1][row] = v.y;
            AsT[kq + 2][row] = v.z;
            AsT[kq + 3][row] = v.w;
        }
        // Load B tile [16][64]. 256 float4, 1/thread. Coalesced.
        {
            const int k = t >> 4;
            const int c = (t & 15) * 4;
            *reinterpret_cast<float4*>(&Bs[k][c]) =
                *reinterpret_cast<const float4*>(Bm + (size_t)(k0 + k) * DIN_ + c);
        }
        __syncthreads();

        #pragma unroll
        for (int k = 0; k < BK; ++k) {
            const float4 a0 = *reinterpret_cast<const float4*>(&AsT[k][rBase]);
            const float4 a1 = *reinterpret_cast<const float4*>(&AsT[k][rBase + 4]);
            const float4 bv = *reinterpret_cast<const float4*>(&Bs[k][colBase]);
            const float av[8] = {a0.x, a0.y, a0.z, a0.w, a1.x, a1.y, a1.z, a1.w};
            #pragma unroll
            for (int i = 0; i < 8; ++i) {
                acc[i][0] += av[i] * bv.x;
                acc[i][1] += av[i] * bv.y;
                acc[i][2] += av[i] * bv.z;
                acc[i][3] += av[i] * bv.w;
            }
        }
        __syncthreads();
    }

    #pragma unroll
    for (int i = 0; i < 8; ++i) {
        const int row = rowBlk + rBase + i;
        float4 v;
        if (MODE == 1) {
            const float4 s = *reinterpret_cast<const float4*>(
                Sub + (size_t)row * DIN_ + colBase);
            v = make_float4(2.f * acc[i][0] - s.x, 2.f * acc[i][1] - s.y,
                            2.f * acc[i][2] - s.z, 2.f * acc[i][3] - s.w);
        } else {
            v = make_float4(acc[i][0], acc[i][1], acc[i][2], acc[i][3]);
        }
        *reinterpret_cast<float4*>(C + (size_t)row * DIN_ + colBase) = v;
    }
}

// ---------------------------------------------------------------------------
// Kernel 3: fused trilinear contraction + STE mix + bias.
// out[n,o] = sum_d STE[n,d] * ( sum_ki h[n,ki] * W[d,ki,o] + bias_pool[d,o] )
// Per block: 128 rows x 64 cols. h tile transposed in smem (hT[ki][n]),
// STE transposed (sT[d][n]), W[d] slice (192x64) streamed through smem per d.
// 256 threads, 8x4 micro-tile; "part" regs hold z[.,d,.] then folded into acc.
// ---------------------------------------------------------------------------
__global__ __launch_bounds__(256) void fused_out_kernel(
    const float* __restrict__ STE,
    const float* __restrict__ Wp,      // [32][3][64][64] = [d][ki][o]
    const float* __restrict__ biasp,   // [32][64]
    float* __restrict__ out)
{
    extern __shared__ float sm[];
    float* hT = sm;                        // [192][128]  96 KB
    float* sT = sm + KI_ * 128;            // [32][128]   16 KB
    float* Ws = sT + ET_ * 128;            // [192][64]   48 KB

    const int b     = blockIdx.y;
    const int nBase = blockIdx.x * 128;
    const int t  = threadIdx.x;
    const int tx = t & 15;
    const int ty = t >> 4;
    const int colBase = tx * 4;
    const int rBase   = ty * 8;

    // Load + transpose h tile: g_h[b][k][nBase+n][i] -> hT[k*64+i][n]
    {
        const float* hsrc = g_h + (size_t)b * (CHEB * NN * DIN_);
        #pragma unroll
        for (int it = 0; it < 24; ++it) {
            const int idx = t + it * 256;      // 0..6143
            const int n  = idx & 127;
            const int ki = (idx >> 7) * 4;     // 0..188
            const int kk = ki >> 6;
            const int i  = ki & 63;
            const float4 v = *reinterpret_cast<const float4*>(
                hsrc + ((size_t)kk * NN + nBase + n) * DIN_ + i);
            hT[(ki + 0) * 128 + n] = v.x;
            hT[(ki + 1) * 128 + n] = v.y;
            hT[(ki + 2) * 128 + n] = v.z;
            hT[(ki + 3) * 128 + n] = v.w;
        }
        // STE[b][nBase+n][d] -> sT[d][n]
        const float* ssrc = STE + ((size_t)b * NN + nBase) * ET_;
        #pragma unroll
        for (int it = 0; it < 4; ++it) {
            const int idx = t + it * 256;      // 0..1023
            const int n = idx & 127;
            const int d = (idx >> 7) * 4;      // 0..28
            const float4 v = *reinterpret_cast<const float4*>(ssrc + n * ET_ + d);
            sT[(d + 0) * 128 + n] = v.x;
            sT[(d + 1) * 128 + n] = v.y;
            sT[(d + 2) * 128 + n] = v.z;
            sT[(d + 3) * 128 + n] = v.w;
        }
    }

    float acc[8][4];
    #pragma unroll
    for (int i = 0; i < 8; ++i)
        #pragma unroll
        for (int j = 0; j < 4; ++j) acc[i][j] = 0.f;

    for (int d = 0; d < ET_; ++d) {
        __syncthreads();   // protect Ws from readers of previous d (also covers hT/sT load at d=0)
        // Stream W[d] slice (192x64 = 3072 float4, 12/thread), coalesced.
        const float* wd = Wp + (size_t)d * KI_ * DOUT_;
        #pragma unroll
        for (int it = 0; it < 12; ++it) {
            const int idx = t + it * 256;
            *reinterpret_cast<float4*>(Ws + idx * 4) =
                *reinterpret_cast<const float4*>(wd + idx * 4);
        }
        __syncthreads();

        float part[8][4];
        #pragma unroll
        for (int i = 0; i < 8; ++i)
            #pragma unroll
            for (int j = 0; j < 4; ++j) part[i][j] = 0.f;

        #pragma unroll 16
        for (int ki = 0; ki < KI_; ++ki) {
            const float4 a0 = *reinterpret_cast<const float4*>(&hT[ki * 128 + rBase]);
            const float4 a1 = *reinterpret_cast<const float4*>(&hT[ki * 128 + rBase + 4]);
            const float4 bv = *reinterpret_cast<const float4*>(&Ws[ki * 64 + colBase]);
            const float av[8] = {a0.x, a0.y, a0.z, a0.w, a1.x, a1.y, a1.z, a1.w};
            #pragma unroll
            for (int i = 0; i < 8; ++i) {
                part[i][0] += av[i] * bv.x;
                part[i][1] += av[i] * bv.y;
                part[i][2] += av[i] * bv.z;
                part[i][3] += av[i] * bv.w;
            }
        }

        // acc += STE[n,d] * (part + bias_pool[d,:])
        const float4 bb = *reinterpret_cast<const float4*>(biasp + d * DOUT_ + colBase);
        const float4 s0 = *reinterpret_cast<const float4*>(&sT[d * 128 + rBase]);
        const float4 s1 = *reinterpret_cast<const float4*>(&sT[d * 128 + rBase + 4]);
        const float sv[8] = {s0.x, s0.y, s0.z, s0.w, s1.x, s1.y, s1.z, s1.w};
        #pragma unroll
        for (int i = 0; i < 8; ++i) {
            acc[i][0] += sv[i] * (part[i][0] + bb.x);
            acc[i][1] += sv[i] * (part[i][1] + bb.y);
            acc[i][2] += sv[i] * (part[i][2] + bb.z);
            acc[i][3] += sv[i] * (part[i][3] + bb.w);
        }
    }

    float* ob = out + ((size_t)b * NN + nBase) * DOUT_;
    #pragma unroll
    for (int i = 0; i < 8; ++i) {
        const float4 v = make_float4(acc[i][0], acc[i][1], acc[i][2], acc[i][3]);
        *reinterpret_cast<float4*>(ob + (size_t)(rBase + i) * DOUT_ + colBase) = v;
    }
}

// ---------------------------------------------------------------------------
// Launch. Input order (metadata): x, STE, R, SC, weights_pool, bias_pool.
// ---------------------------------------------------------------------------
extern "C" void kernel_launch(void* const* d_in, const int* in_sizes, int n_in,
                              void* d_out, int out_size)
{
    (void)in_sizes; (void)n_in; (void)out_size;
    const float* x     = (const float*)d_in[0];
    const float* STE   = (const float*)d_in[1];
    const float* R     = (const float*)d_in[2];
    const float* SC    = (const float*)d_in[3];
    const float* Wp    = (const float*)d_in[4];
    const float* biasp = (const float*)d_in[5];
    float* out = (float*)d_out;

    const int SMEM3 = (KI_ * 128 + ET_ * 128 + KI_ * DOUT_) * (int)sizeof(float); // 160 KB
    // Idempotent; not a stream op, so safe under graph capture.
    cudaFuncSetAttribute(fused_out_kernel,
                         cudaFuncAttributeMaxDynamicSharedMemorySize, SMEM3);

    // h0 = SC@x, h1 = R@x   (grid.z selects matrix)
    prop_gemm<0><<<dim3(NN / 128, NB, 2), 256>>>(R, SC, x);
    // h2 = 2*R@h1 - h0
    prop_gemm<1><<<dim3(NN / 128, NB, 1), 256>>>(R, SC, x);
    // out = sum_d STE .* (h @ W[d] + bias[d])
    fused_out_kernel<<<dim3(NN / 128, NB), 256, SMEM3>>>(STE, Wp, biasp, out);
}

// round 4
// speedup vs baseline: 1.4292x; 1.4292x over previous
#include <cuda_runtime.h>
#include <cuda_bf16.h>
#include <cstdint>
#include <cstddef>

// Problem constants
#define NB    32
#define NN    512
#define DIN_  64
#define DOUT_ 64
#define ET_   32
#define CHEB  3
#define KI_   (CHEB * DIN_)   // 192

// Scratch: h[b][k][n][i]  fp32 (12.6 MB)
__device__ float g_h[(size_t)NB * CHEB * NN * DIN_];

// ===========================================================================
// mma.sync machinery (sm_80+ PTX; no 'a'-gated features)
// ===========================================================================
__device__ __forceinline__ uint32_t smem_u32(const void* p) {
    uint32_t a;
    asm("{ .reg .u64 t; cvta.to.shared.u64 t, %1; cvt.u32.u64 %0, t; }"
        : "=r"(a) : "l"(p));
    return a;
}

__device__ __forceinline__ void ldsm_x4(uint32_t& r0, uint32_t& r1,
                                        uint32_t& r2, uint32_t& r3, uint32_t addr) {
    asm volatile("ldmatrix.sync.aligned.m8n8.x4.shared.b16 {%0,%1,%2,%3}, [%4];"
                 : "=r"(r0), "=r"(r1), "=r"(r2), "=r"(r3) : "r"(addr));
}

__device__ __forceinline__ void ldsm_x2t(uint32_t& r0, uint32_t& r1, uint32_t addr) {
    asm volatile("ldmatrix.sync.aligned.m8n8.x2.trans.shared.b16 {%0,%1}, [%2];"
                 : "=r"(r0), "=r"(r1) : "r"(addr));
}

__device__ __forceinline__ void mma_bf16(float* c, const uint32_t* a,
                                         uint32_t b0, uint32_t b1) {
    asm volatile(
        "mma.sync.aligned.m16n8k16.row.col.f32.bf16.bf16.f32 "
        "{%0,%1,%2,%3}, {%4,%5,%6,%7}, {%8,%9}, {%0,%1,%2,%3};"
        : "+f"(c[0]), "+f"(c[1]), "+f"(c[2]), "+f"(c[3])
        : "r"(a[0]), "r"(a[1]), "r"(a[2]), "r"(a[3]), "r"(b0), "r"(b1));
}

// Split p0,p1 into bf16 hi/lo pairs and store at (hiAddr, loAddr) as bf16x2.
__device__ __forceinline__ void split_store2(char* hiP, char* loP, float p0, float p1) {
    __nv_bfloat16 h0 = __float2bfloat16_rn(p0);
    __nv_bfloat16 h1 = __float2bfloat16_rn(p1);
    __nv_bfloat16 l0 = __float2bfloat16_rn(p0 - __bfloat162float(h0));
    __nv_bfloat16 l1 = __float2bfloat16_rn(p1 - __bfloat162float(h1));
    __nv_bfloat162 vh; vh.x = h0; vh.y = h1;
    __nv_bfloat162 vl; vl.x = l0; vl.y = l1;
    *reinterpret_cast<__nv_bfloat162*>(hiP) = vh;
    *reinterpret_cast<__nv_bfloat162*>(loP) = vl;
}

// Tile row strides: 72 bf16 = 144 B = 16B x 9 (odd) -> ldmatrix conflict-free.
#define TSTRIDE_B 144u

// One K=16*ksteps MMA pass over A[128][..] x B[..][64] tiles (hi/lo split, 3 products).
// Warp grid: wy = wid>>1 (4 row groups of 32), wx = wid&1 (2 col groups of 32).
// acc[mt][nt][4] for mt in 0..1 (16-row tiles), nt in 0..3 (8-col tiles).
__device__ __forceinline__ void mma_tiles(float acc[2][4][4],
                                          uint32_t aH, uint32_t aL,
                                          uint32_t bH, uint32_t bL,
                                          int wy, int wx, int lane, int ksteps) {
    const uint32_t rowSel = (uint32_t)(wy * 32 + (lane & 15));
    const uint32_t kSel   = (uint32_t)((lane >> 4) << 3);       // +8 for upper lanes
    const uint32_t kSelB  = (uint32_t)(lane & 15);              // B: k row = kb + (lane&15)
    for (int ks = 0; ks < ksteps; ++ks) {
        const uint32_t kb = (uint32_t)(ks * 16);
        uint32_t ah[2][4], al[2][4];
        #pragma unroll
        for (int mt = 0; mt < 2; ++mt) {
            const uint32_t off = (rowSel + (uint32_t)(mt * 16)) * TSTRIDE_B + (kb + kSel) * 2u;
            ldsm_x4(ah[mt][0], ah[mt][1], ah[mt][2], ah[mt][3], aH + off);
            ldsm_x4(al[mt][0], al[mt][1], al[mt][2], al[mt][3], aL + off);
        }
        #pragma unroll
        for (int nt = 0; nt < 4; ++nt) {
            const uint32_t ob  = (uint32_t)(wx * 32 + nt * 8);
            const uint32_t off = (kb + kSelB) * TSTRIDE_B + ob * 2u;
            uint32_t bh0, bh1, bl0, bl1;
            ldsm_x2t(bh0, bh1, bH + off);
            ldsm_x2t(bl0, bl1, bL + off);
            #pragma unroll
            for (int mt = 0; mt < 2; ++mt) {
                mma_bf16(acc[mt][nt], ah[mt], bh0, bh1);
                mma_bf16(acc[mt][nt], ah[mt], bl0, bl1);
                mma_bf16(acc[mt][nt], al[mt], bh0, bh1);
            }
        }
    }
}

// ===========================================================================
// Kernel 1/2: per-batch C[512x64] = A[512x512] @ Bm[512x64] via bf16-split MMA.
// MODE 0: z selects SC->h0 / R->h1, Bm=x.  MODE 1: A=R, Bm=h1, C=2*acc-h0 -> h2
// ===========================================================================
#define P_OFF_AH 0
#define P_OFF_AL 18432
#define P_OFF_BH 36864
#define P_OFF_BL 46080
#define P_SMEM   55296

template<int MODE>
__global__ __launch_bounds__(256) void prop_mma(
    const float* __restrict__ R,
    const float* __restrict__ SC,
    const float* __restrict__ X)
{
    extern __shared__ char smem[];
    const int b = blockIdx.y;
    const int rowBlk = blockIdx.x * 128;

    float* hb = g_h + (size_t)b * (CHEB * NN * DIN_);
    const float* A;
    const float* Bm;
    const float* Sub = nullptr;
    float* C;
    if (MODE == 0) {
        const int which = blockIdx.z;
        A  = (which == 0 ? SC : R) + (size_t)b * NN * NN;
        Bm = X + (size_t)b * NN * DIN_;
        C  = hb + (size_t)which * NN * DIN_;
    } else {
        A   = R  + (size_t)b * NN * NN;
        Bm  = hb + (size_t)1 * NN * DIN_;
        Sub = hb + (size_t)0 * NN * DIN_;
        C   = hb + (size_t)2 * NN * DIN_;
    }

    const int t    = threadIdx.x;
    const int wid  = t >> 5;
    const int lane = t & 31;
    const int wy   = wid >> 1;
    const int wx   = wid & 1;

    const uint32_t sb = smem_u32(smem);
    const uint32_t aHu = sb + P_OFF_AH, aLu = sb + P_OFF_AL;
    const uint32_t bHu = sb + P_OFF_BH, bLu = sb + P_OFF_BL;

    float acc[2][4][4];
    #pragma unroll
    for (int mt = 0; mt < 2; ++mt)
        #pragma unroll
        for (int nt = 0; nt < 4; ++nt)
            #pragma unroll
            for (int e = 0; e < 4; ++e) acc[mt][nt][e] = 0.f;

    for (int kc = 0; kc < 8; ++kc) {
        __syncthreads();
        // Build A chunk [128 n][64 k] hi/lo
        #pragma unroll
        for (int it = 0; it < 8; ++it) {
            const int idx = t + it * 256;          // 0..2047 float4s
            const int n  = idx >> 4;
            const int j4 = (idx & 15) * 4;
            const float4 v = *reinterpret_cast<const float4*>(
                A + (size_t)(rowBlk + n) * NN + kc * 64 + j4);
            char* hp = smem + P_OFF_AH + n * TSTRIDE_B + j4 * 2;
            char* lp = smem + P_OFF_AL + n * TSTRIDE_B + j4 * 2;
            split_store2(hp,     lp,     v.x, v.y);
            split_store2(hp + 4, lp + 4, v.z, v.w);
        }
        // Build B chunk [64 k][64 i] hi/lo (k-major, natural layout)
        #pragma unroll
        for (int it = 0; it < 4; ++it) {
            const int idx = t + it * 256;          // 0..1023 float4s
            const int k  = idx >> 4;
            const int i4 = (idx & 15) * 4;
            const float4 v = *reinterpret_cast<const float4*>(
                Bm + (size_t)(kc * 64 + k) * DIN_ + i4);
            char* hp = smem + P_OFF_BH + k * TSTRIDE_B + i4 * 2;
            char* lp = smem + P_OFF_BL + k * TSTRIDE_B + i4 * 2;
            split_store2(hp,     lp,     v.x, v.y);
            split_store2(hp + 4, lp + 4, v.z, v.w);
        }
        __syncthreads();
        mma_tiles(acc, aHu, aLu, bHu, bLu, wy, wx, lane, 4);
    }

    // Epilogue
    const int r0   = rowBlk + wy * 32 + (lane >> 2);
    const int col0 = wx * 32 + 2 * (lane & 3);
    #pragma unroll
    for (int mt = 0; mt < 2; ++mt) {
        #pragma unroll
        for (int nt = 0; nt < 4; ++nt) {
            const int row = r0 + mt * 16;
            const int cc  = col0 + nt * 8;
            float2 v0, v1;
            if (MODE == 1) {
                const float2 s0 = *reinterpret_cast<const float2*>(Sub + (size_t)row * DIN_ + cc);
                const float2 s1 = *reinterpret_cast<const float2*>(Sub + (size_t)(row + 8) * DIN_ + cc);
                v0 = make_float2(2.f * acc[mt][nt][0] - s0.x, 2.f * acc[mt][nt][1] - s0.y);
                v1 = make_float2(2.f * acc[mt][nt][2] - s1.x, 2.f * acc[mt][nt][3] - s1.y);
            } else {
                v0 = make_float2(acc[mt][nt][0], acc[mt][nt][1]);
                v1 = make_float2(acc[mt][nt][2], acc[mt][nt][3]);
            }
            *reinterpret_cast<float2*>(C + (size_t)row * DIN_ + cc)       = v0;
            *reinterpret_cast<float2*>(C + (size_t)(row + 8) * DIN_ + cc) = v1;
        }
    }
}

// ===========================================================================
// Kernel 3: fused contraction via bf16-split MMA.
// out[n,o] = sum_d (STE[n,d]*h[n,:]) @ W[d][:,o]  +  STE[n,:] @ bias_pool[:,o]
// 97 chunks: 96 = (d, kc) with K=64, + 1 bias chunk with K=32.
// ===========================================================================
#define F_OFF_H   0          // fp32 [128][196]  100352 B
#define F_OFF_S   100352     // fp32 [128][36]    18432 B
#define F_OFF_AH  118784     // bf16 [128][72]    18432 B
#define F_OFF_AL  137216
#define F_OFF_BH  155648     // bf16 [64][72]      9216 B
#define F_OFF_BL  164864
#define F_SMEM    174080
#define HSTR      196
#define SSTR      36

__global__ __launch_bounds__(256) void fused_mma(
    const float* __restrict__ STE,
    const float* __restrict__ Wp,      // [d][ki][o]
    const float* __restrict__ biasp,   // [d][o]
    float* __restrict__ out)
{
    extern __shared__ char smem[];
    const int b     = blockIdx.y;
    const int nBase = blockIdx.x * 128;
    const int t    = threadIdx.x;
    const int wid  = t >> 5;
    const int lane = t & 31;
    const int wy   = wid >> 1;
    const int wx   = wid & 1;

    const uint32_t sb = smem_u32(smem);
    const uint32_t aHu = sb + F_OFF_AH, aLu = sb + F_OFF_AL;
    const uint32_t bHu = sb + F_OFF_BH, bLu = sb + F_OFF_BL;
    float* hS = reinterpret_cast<float*>(smem + F_OFF_H);
    float* sS = reinterpret_cast<float*>(smem + F_OFF_S);

    // Stage h (fp32) and STE (fp32)
    {
        const float* hsrc = g_h + (size_t)b * (CHEB * NN * DIN_);
        #pragma unroll
        for (int it = 0; it < 24; ++it) {
            const int idx = t + it * 256;          // 0..6143 float4s
            const int i4 = (idx & 15) * 4;
            const int n  = (idx >> 4) & 127;
            const int k  = idx >> 11;              // 0..2
            const float4 v = *reinterpret_cast<const float4*>(
                hsrc + ((size_t)k * NN + nBase + n) * DIN_ + i4);
            float* dr = hS + n * HSTR + k * 64 + i4;
            dr[0] = v.x; dr[1] = v.y; dr[2] = v.z; dr[3] = v.w;
        }
        const float* ssrc = STE + ((size_t)b * NN + nBase) * ET_;
        #pragma unroll
        for (int it = 0; it < 4; ++it) {
            const int idx = t + it * 256;          // 0..1023 float4s
            const int d4 = (idx & 7) * 4;
            const int n  = idx >> 3;
            const float4 v = *reinterpret_cast<const float4*>(ssrc + n * ET_ + d4);
            float* dr = sS + n * SSTR + d4;
            dr[0] = v.x; dr[1] = v.y; dr[2] = v.z; dr[3] = v.w;
        }
    }

    float acc[2][4][4];
    #pragma unroll
    for (int mt = 0; mt < 2; ++mt)
        #pragma unroll
        for (int nt = 0; nt < 4; ++nt)
            #pragma unroll
            for (int e = 0; e < 4; ++e) acc[mt][nt][e] = 0.f;

    int d = 0, kc = 0;
    for (int c = 0; c < 97; ++c) {
        __syncthreads();   // tiles consumed; safe to overwrite (also orders staging at c=0)
        if (c < 96) {
            // A chunk: A[n][j] = STE[n,d] * h[n][kc*64+j]
            {
                const int n  = t >> 1;
                const int jh = (t & 1) * 32;
                const float s   = sS[n * SSTR + d];
                const float* hr = hS + n * HSTR + kc * 64;
                char* hp = smem + F_OFF_AH + n * TSTRIDE_B + jh * 2;
                char* lp = smem + F_OFF_AL + n * TSTRIDE_B + jh * 2;
                #pragma unroll
                for (int u = 0; u < 16; ++u) {
                    const float2 hv = *reinterpret_cast<const float2*>(hr + jh + 2 * u);
                    split_store2(hp + 4 * u, lp + 4 * u, s * hv.x, s * hv.y);
                }
            }
            // B chunk: B[k][o] = W[d][kc*64+k][o]  (k-major, natural)
            {
                const float* wd = Wp + ((size_t)d * KI_ + kc * 64) * DOUT_;
                #pragma unroll
                for (int it = 0; it < 4; ++it) {
                    const int idx = t + it * 256;     // 0..1023
                    const int k  = idx >> 4;
                    const int o4 = (idx & 15) * 4;
                    const float4 v = *reinterpret_cast<const float4*>(wd + (size_t)k * DOUT_ + o4);
                    char* hp = smem + F_OFF_BH + k * TSTRIDE_B + o4 * 2;
                    char* lp = smem + F_OFF_BL + k * TSTRIDE_B + o4 * 2;
                    split_store2(hp,     lp,     v.x, v.y);
                    split_store2(hp + 4, lp + 4, v.z, v.w);
                }
            }
        } else {
            // Bias chunk (K=32): A[n][j] = STE[n][j], B[j][o] = bias[j][o]
            if ((t & 1) == 0) {
                const int n = t >> 1;
                char* hp = smem + F_OFF_AH + n * TSTRIDE_B;
                char* lp = smem + F_OFF_AL + n * TSTRIDE_B;
                const float* sr = sS + n * SSTR;
                #pragma unroll
                for (int u = 0; u < 16; ++u)
                    split_store2(hp + 4 * u, lp + 4 * u, sr[2 * u], sr[2 * u + 1]);
            }
            #pragma unroll
            for (int it = 0; it < 2; ++it) {
                const int idx = t + it * 256;        // 0..511
                const int k  = idx >> 4;             // 0..31
                const int o4 = (idx & 15) * 4;
                const float4 v = *reinterpret_cast<const float4*>(biasp + (size_t)k * DOUT_ + o4);
                char* hp = smem + F_OFF_BH + k * TSTRIDE_B + o4 * 2;
                char* lp = smem + F_OFF_BL + k * TSTRIDE_B + o4 * 2;
                split_store2(hp,     lp,     v.x, v.y);
                split_store2(hp + 4, lp + 4, v.z, v.w);
            }
        }
        __syncthreads();
        mma_tiles(acc, aHu, aLu, bHu, bLu, wy, wx, lane, (c == 96) ? 2 : 4);
        if (++kc == 3) { kc = 0; ++d; }
    }

    // Epilogue
    const int r0   = nBase + wy * 32 + (lane >> 2);
    const int col0 = wx * 32 + 2 * (lane & 3);
    float* ob = out + (size_t)b * NN * DOUT_;
    #pragma unroll
    for (int mt = 0; mt < 2; ++mt) {
        #pragma unroll
        for (int nt = 0; nt < 4; ++nt) {
            const int row = r0 + mt * 16;
            const int cc  = col0 + nt * 8;
            *reinterpret_cast<float2*>(ob + (size_t)row * DOUT_ + cc) =
                make_float2(acc[mt][nt][0], acc[mt][nt][1]);
            *reinterpret_cast<float2*>(ob + (size_t)(row + 8) * DOUT_ + cc) =
                make_float2(acc[mt][nt][2], acc[mt][nt][3]);
        }
    }
}

// ===========================================================================
// Launch. Inputs: x, STE, R, SC, weights_pool, bias_pool.
// ===========================================================================
extern "C" void kernel_launch(void* const* d_in, const int* in_sizes, int n_in,
                              void* d_out, int out_size)
{
    (void)in_sizes; (void)n_in; (void)out_size;
    const float* x     = (const float*)d_in[0];
    const float* STE   = (const float*)d_in[1];
    const float* R     = (const float*)d_in[2];
    const float* SC    = (const float*)d_in[3];
    const float* Wp    = (const float*)d_in[4];
    const float* biasp = (const float*)d_in[5];
    float* out = (float*)d_out;

    cudaFuncSetAttribute(prop_mma<0>, cudaFuncAttributeMaxDynamicSharedMemorySize, P_SMEM);
    cudaFuncSetAttribute(prop_mma<1>, cudaFuncAttributeMaxDynamicSharedMemorySize, P_SMEM);
    cudaFuncSetAttribute(fused_mma,   cudaFuncAttributeMaxDynamicSharedMemorySize, F_SMEM);

    prop_mma<0><<<dim3(NN / 128, NB, 2), 256, P_SMEM>>>(R, SC, x);
    prop_mma<1><<<dim3(NN / 128, NB, 1), 256, P_SMEM>>>(R, SC, x);
    fused_mma<<<dim3(NN / 128, NB), 256, F_SMEM>>>(STE, Wp, biasp, out);
}

// round 5
// speedup vs baseline: 1.7518x; 1.2258x over previous
#include <cuda_runtime.h>
#include <cuda_bf16.h>
#include <cstdint>
#include <cstddef>

// Problem constants
#define NB    32
#define NN    512
#define DIN_  64
#define DOUT_ 64
#define ET_   32
#define CHEB  3
#define KI_   (CHEB * DIN_)   // 192

// Scratch: h[b][k][n][i]  fp32 (12.6 MB)
__device__ float g_h[(size_t)NB * CHEB * NN * DIN_];
// Pre-split W (+bias as chunk 96): [97 chunks][64 rows][72 cols] bf16 (144B rows)
__device__ __align__(16) __nv_bfloat16 g_WsHi[97 * 64 * 72];
__device__ __align__(16) __nv_bfloat16 g_WsLo[97 * 64 * 72];

// Tile row stride: 72 bf16 = 144 B (odd multiple of 16B -> ldmatrix conflict-free)
#define TSTR 144u

// ===========================================================================
// PTX helpers
// ===========================================================================
__device__ __forceinline__ uint32_t smem_u32(const void* p) {
    uint32_t a;
    asm("{ .reg .u64 t; cvta.to.shared.u64 t, %1; cvt.u32.u64 %0, t; }"
        : "=r"(a) : "l"(p));
    return a;
}
__device__ __forceinline__ void ldsm_x4(uint32_t& r0, uint32_t& r1,
                                        uint32_t& r2, uint32_t& r3, uint32_t addr) {
    asm volatile("ldmatrix.sync.aligned.m8n8.x4.shared.b16 {%0,%1,%2,%3}, [%4];"
                 : "=r"(r0), "=r"(r1), "=r"(r2), "=r"(r3) : "r"(addr));
}
__device__ __forceinline__ void ldsm_x2t(uint32_t& r0, uint32_t& r1, uint32_t addr) {
    asm volatile("ldmatrix.sync.aligned.m8n8.x2.trans.shared.b16 {%0,%1}, [%2];"
                 : "=r"(r0), "=r"(r1) : "r"(addr));
}
__device__ __forceinline__ void mma_bf16(float* c, const uint32_t* a,
                                         uint32_t b0, uint32_t b1) {
    asm volatile(
        "mma.sync.aligned.m16n8k16.row.col.f32.bf16.bf16.f32 "
        "{%0,%1,%2,%3}, {%4,%5,%6,%7}, {%8,%9}, {%0,%1,%2,%3};"
        : "+f"(c[0]), "+f"(c[1]), "+f"(c[2]), "+f"(c[3])
        : "r"(a[0]), "r"(a[1]), "r"(a[2]), "r"(a[3]), "r"(b0), "r"(b1));
}
__device__ __forceinline__ void cp16(uint32_t dst, const void* src) {
    asm volatile("cp.async.ca.shared.global [%0], [%1], 16;" :: "r"(dst), "l"(src));
}
#define CP_COMMIT() asm volatile("cp.async.commit_group;" ::: "memory")
#define CP_WAIT0()  asm volatile("cp.async.wait_group 0;" ::: "memory")
__device__ __forceinline__ void bar_sync(int id) {
    asm volatile("bar.sync %0, 256;" :: "r"(id) : "memory");
}
__device__ __forceinline__ void bar_arrive(int id) {
    asm volatile("bar.arrive %0, 256;" :: "r"(id) : "memory");
}
// Barrier ids: FULL buf0/1 = 1/2, EMPTY buf0/1 = 3/4
#define BAR_FULL  1
#define BAR_EMPTY 3

// pack two floats into bf16x2 (p0 -> low half, p1 -> high half)
__device__ __forceinline__ uint32_t pack2(float p0, float p1) {
    uint32_t r;
    asm("cvt.rn.bf16x2.f32 %0, %1, %2;" : "=r"(r) : "f"(p1), "f"(p0));
    return r;
}
// split pair -> (hi bf16x2, lo bf16x2)
__device__ __forceinline__ void split2(float p0, float p1, uint32_t& uh, uint32_t& ul) {
    uh = pack2(p0, p1);
    const float h0 = __uint_as_float(uh << 16);
    const float h1 = __uint_as_float(uh & 0xffff0000u);
    ul = pack2(p0 - h0, p1 - h1);
}

// ===========================================================================
// Consumer: one K=16*ksteps MMA pass. 4 warps x 32 rows x 64 cols.
// acc[mt][nt][4], mt 0..1 (16-row), nt 0..7 (8-col).
// ===========================================================================
__device__ __forceinline__ void mma_chunk(float acc[2][8][4],
                                          uint32_t aH, uint32_t aL,
                                          uint32_t bH, uint32_t bL,
                                          int warp, int lane, int ksteps) {
    const uint32_t rowSel = (uint32_t)(warp * 32 + (lane & 15));
    const uint32_t kSel   = (uint32_t)((lane >> 4) << 3);
    const uint32_t kSelB  = (uint32_t)(lane & 15);
    for (int ks = 0; ks < ksteps; ++ks) {
        const uint32_t kb = (uint32_t)(ks * 16);
        uint32_t ah[2][4], al[2][4];
        #pragma unroll
        for (int mt = 0; mt < 2; ++mt) {
            const uint32_t off = (rowSel + (uint32_t)(mt * 16)) * TSTR + (kb + kSel) * 2u;
            ldsm_x4(ah[mt][0], ah[mt][1], ah[mt][2], ah[mt][3], aH + off);
            ldsm_x4(al[mt][0], al[mt][1], al[mt][2], al[mt][3], aL + off);
        }
        #pragma unroll
        for (int nt = 0; nt < 8; ++nt) {
            const uint32_t off = (kb + kSelB) * TSTR + (uint32_t)(nt * 16);
            uint32_t bh0, bh1, bl0, bl1;
            ldsm_x2t(bh0, bh1, bH + off);
            ldsm_x2t(bl0, bl1, bL + off);
            #pragma unroll
            for (int mt = 0; mt < 2; ++mt) {
                mma_bf16(acc[mt][nt], ah[mt], bh0, bh1);
                mma_bf16(acc[mt][nt], ah[mt], bl0, bl1);
                mma_bf16(acc[mt][nt], al[mt], bh0, bh1);
            }
        }
    }
}

// ===========================================================================
// Precompute: split W (+bias chunk 96) into padded bf16 hi/lo tiles.
// ===========================================================================
__global__ __launch_bounds__(256) void prep_w(const float* __restrict__ Wp,
                                              const float* __restrict__ biasp) {
    const int c = blockIdx.x;
    const int t = threadIdx.x;
    __nv_bfloat16* hi = g_WsHi + (size_t)c * 64 * 72;
    __nv_bfloat16* lo = g_WsLo + (size_t)c * 64 * 72;
    #pragma unroll
    for (int it = 0; it < 4; ++it) {
        const int idx = t + it * 256;        // 0..1023
        const int k  = idx >> 4;
        const int o4 = (idx & 15) * 4;
        float4 v = make_float4(0.f, 0.f, 0.f, 0.f);
        if (c < 96) {
            const int d = c / 3, kc = c - d * 3;
            v = *reinterpret_cast<const float4*>(Wp + ((size_t)(d * KI_ + kc * 64 + k)) * DOUT_ + o4);
        } else if (k < 32) {
            v = *reinterpret_cast<const float4*>(biasp + (size_t)k * DOUT_ + o4);
        }
        uint32_t h0, l0, h1, l1;
        split2(v.x, v.y, h0, l0);
        split2(v.z, v.w, h1, l1);
        *reinterpret_cast<uint2*>(hi + k * 72 + o4) = make_uint2(h0, h1);
        *reinterpret_cast<uint2*>(lo + k * 72 + o4) = make_uint2(l0, l1);
    }
    if (t < 64) {   // zero the 16B pad of each row
        *reinterpret_cast<uint4*>(hi + t * 72 + 64) = make_uint4(0, 0, 0, 0);
        *reinterpret_cast<uint4*>(lo + t * 72 + 64) = make_uint4(0, 0, 0, 0);
    }
}

// ===========================================================================
// Prop kernels: C[512x64] = A[512x512] @ Bm[512x64], warp-specialized.
// MODE 0: z selects SC->h0 / R->h1, Bm=x.  MODE 1: A=R, Bm=h1, C=2*acc-h0 -> h2
// smem: 2 buffers x {AH 18432 | AL 18432 | BH 9216 | BL 9216} = 110592 B
// ===========================================================================
#define BUFSZ   55296
#define OB_AL   18432
#define OB_BH   36864
#define OB_BL   46080
#define P_SMEM  (2 * BUFSZ)

template<int MODE>
__global__ __launch_bounds__(256, 1) void prop_mma(
    const float* __restrict__ R,
    const float* __restrict__ SC,
    const float* __restrict__ X)
{
    extern __shared__ char smem[];
    const int b = blockIdx.y;
    const int rowBlk = blockIdx.x * 128;

    float* hb = g_h + (size_t)b * (CHEB * NN * DIN_);
    const float* A;
    const float* Bm;
    const float* Sub = nullptr;
    float* C;
    if (MODE == 0) {
        const int which = blockIdx.z;
        A  = (which == 0 ? SC : R) + (size_t)b * NN * NN;
        Bm = X + (size_t)b * NN * DIN_;
        C  = hb + (size_t)which * NN * DIN_;
    } else {
        A   = R  + (size_t)b * NN * NN;
        Bm  = hb + (size_t)1 * NN * DIN_;
        Sub = hb + (size_t)0 * NN * DIN_;
        C   = hb + (size_t)2 * NN * DIN_;
    }

    const int t    = threadIdx.x;
    const int wid  = t >> 5;
    const int lane = t & 31;
    const uint32_t sb = smem_u32(smem);

    if (wid < 4) {
        // ---------------- consumer ----------------
        float acc[2][8][4];
        #pragma unroll
        for (int mt = 0; mt < 2; ++mt)
            #pragma unroll
            for (int nt = 0; nt < 8; ++nt)
                #pragma unroll
                for (int e = 0; e < 4; ++e) acc[mt][nt][e] = 0.f;

        for (int c = 0; c < 8; ++c) {
            const int buf = c & 1;
            const uint32_t base = sb + buf * BUFSZ;
            bar_sync(BAR_FULL + buf);
            mma_chunk(acc, base, base + OB_AL, base + OB_BH, base + OB_BL, wid, lane, 4);
            bar_arrive(BAR_EMPTY + buf);
        }
        // epilogue
        const int r0   = rowBlk + wid * 32 + (lane >> 2);
        const int col0 = 2 * (lane & 3);
        #pragma unroll
        for (int mt = 0; mt < 2; ++mt) {
            #pragma unroll
            for (int nt = 0; nt < 8; ++nt) {
                const int row = r0 + mt * 16;
                const int cc  = col0 + nt * 8;
                float2 v0, v1;
                if (MODE == 1) {
                    const float2 s0 = *reinterpret_cast<const float2*>(Sub + (size_t)row * DIN_ + cc);
                    const float2 s1 = *reinterpret_cast<const float2*>(Sub + (size_t)(row + 8) * DIN_ + cc);
                    v0 = make_float2(2.f * acc[mt][nt][0] - s0.x, 2.f * acc[mt][nt][1] - s0.y);
                    v1 = make_float2(2.f * acc[mt][nt][2] - s1.x, 2.f * acc[mt][nt][3] - s1.y);
                } else {
                    v0 = make_float2(acc[mt][nt][0], acc[mt][nt][1]);
                    v1 = make_float2(acc[mt][nt][2], acc[mt][nt][3]);
                }
                *reinterpret_cast<float2*>(C + (size_t)row * DIN_ + cc)       = v0;
                *reinterpret_cast<float2*>(C + (size_t)(row + 8) * DIN_ + cc) = v1;
            }
        }
    } else {
        // ---------------- producer ----------------
        const int pt = t - 128;
        for (int c = 0; c < 8; ++c) {
            const int buf = c & 1;
            const uint32_t base = sb + buf * BUFSZ;
            char* baseP = smem + buf * BUFSZ;
            if (c >= 2) bar_sync(BAR_EMPTY + buf);
            (void)base;
            // A chunk [128 n][64 k]: 2048 float4s, 16 per thread, coalesced
            #pragma unroll
            for (int q = 0; q < 16; ++q) {
                const int idx = pt + q * 128;
                const int n  = idx >> 4;
                const int j4 = (idx & 15) * 4;
                const float4 v = *reinterpret_cast<const float4*>(
                    A + (size_t)(rowBlk + n) * NN + c * 64 + j4);
                uint32_t h0, l0, h1, l1;
                split2(v.x, v.y, h0, l0);
                split2(v.z, v.w, h1, l1);
                *reinterpret_cast<uint2*>(baseP + n * TSTR + j4 * 2)         = make_uint2(h0, h1);
                *reinterpret_cast<uint2*>(baseP + OB_AL + n * TSTR + j4 * 2) = make_uint2(l0, l1);
            }
            // B chunk [64 k][64 i]: 1024 float4s, 8 per thread
            #pragma unroll
            for (int q = 0; q < 8; ++q) {
                const int idx = pt + q * 128;
                const int k  = idx >> 4;
                const int i4 = (idx & 15) * 4;
                const float4 v = *reinterpret_cast<const float4*>(
                    Bm + (size_t)(c * 64 + k) * DIN_ + i4);
                uint32_t h0, l0, h1, l1;
                split2(v.x, v.y, h0, l0);
                split2(v.z, v.w, h1, l1);
                *reinterpret_cast<uint2*>(baseP + OB_BH + k * TSTR + i4 * 2) = make_uint2(h0, h1);
                *reinterpret_cast<uint2*>(baseP + OB_BL + k * TSTR + i4 * 2) = make_uint2(l0, l1);
            }
            bar_arrive(BAR_FULL + buf);
        }
    }
}

// ===========================================================================
// Fused contraction: out[n,o] = sum_d (STE[n,d]*h[n,:]) @ W[d] + STE @ bias.
// 97 chunks (96 K=64 + bias K=32). Producers: A = STE-scaled h split (from
// transposed smem staging), B = cp.async of precomputed W split tiles.
// smem: tiles 110592 | hT fp32 [192][132] 101376 | sT fp32 [32][128] 16384
// ===========================================================================
#define F_OFF_HT 110592
#define F_OFF_ST 211968
#define F_SMEM   228352
#define HT_STR   132

__global__ __launch_bounds__(256, 1) void fused_mma(
    const float* __restrict__ STE,
    float* __restrict__ out)
{
    extern __shared__ char smem[];
    const int b     = blockIdx.y;
    const int nBase = blockIdx.x * 128;
    const int t    = threadIdx.x;
    const int wid  = t >> 5;
    const int lane = t & 31;
    const uint32_t sb = smem_u32(smem);
    float* hT = reinterpret_cast<float*>(smem + F_OFF_HT);
    float* sT = reinterpret_cast<float*>(smem + F_OFF_ST);

    // ---- staging (all 256 threads): transposed h and STE ----
    {
        const float* hsrc = g_h + (size_t)b * (CHEB * NN * DIN_);
        #pragma unroll
        for (int it = 0; it < 24; ++it) {
            const int idx = t + it * 256;          // 0..6143 float4s
            const int i4 = (idx & 15) * 4;
            const int n  = (idx >> 4) & 127;
            const int k  = idx >> 11;              // 0..2
            const float4 v = *reinterpret_cast<const float4*>(
                hsrc + ((size_t)k * NN + nBase + n) * DIN_ + i4);
            const int r = k * 64 + i4;
            hT[(r + 0) * HT_STR + n] = v.x;
            hT[(r + 1) * HT_STR + n] = v.y;
            hT[(r + 2) * HT_STR + n] = v.z;
            hT[(r + 3) * HT_STR + n] = v.w;
        }
        const float* ssrc = STE + ((size_t)b * NN + nBase) * ET_;
        #pragma unroll
        for (int it = 0; it < 4; ++it) {
            const int idx = t + it * 256;          // 0..1023 float4s
            const int d4 = (idx & 7) * 4;
            const int n  = idx >> 3;
            const float4 v = *reinterpret_cast<const float4*>(ssrc + n * ET_ + d4);
            sT[(d4 + 0) * 128 + n] = v.x;
            sT[(d4 + 1) * 128 + n] = v.y;
            sT[(d4 + 2) * 128 + n] = v.z;
            sT[(d4 + 3) * 128 + n] = v.w;
        }
    }
    __syncthreads();

    if (wid < 4) {
        // ---------------- consumer ----------------
        float acc[2][8][4];
        #pragma unroll
        for (int mt = 0; mt < 2; ++mt)
            #pragma unroll
            for (int nt = 0; nt < 8; ++nt)
                #pragma unroll
                for (int e = 0; e < 4; ++e) acc[mt][nt][e] = 0.f;

        for (int c = 0; c < 97; ++c) {
            const int buf = c & 1;
            const uint32_t base = sb + buf * BUFSZ;
            bar_sync(BAR_FULL + buf);
            mma_chunk(acc, base, base + OB_AL, base + OB_BH, base + OB_BL,
                      wid, lane, (c == 96) ? 2 : 4);
            bar_arrive(BAR_EMPTY + buf);
        }
        // epilogue
        const int r0   = nBase + wid * 32 + (lane >> 2);
        const int col0 = 2 * (lane & 3);
        float* ob = out + (size_t)b * NN * DOUT_;
        #pragma unroll
        for (int mt = 0; mt < 2; ++mt) {
            #pragma unroll
            for (int nt = 0; nt < 8; ++nt) {
                const int row = r0 + mt * 16;
                const int cc  = col0 + nt * 8;
                *reinterpret_cast<float2*>(ob + (size_t)row * DOUT_ + cc) =
                    make_float2(acc[mt][nt][0], acc[mt][nt][1]);
                *reinterpret_cast<float2*>(ob + (size_t)(row + 8) * DOUT_ + cc) =
                    make_float2(acc[mt][nt][2], acc[mt][nt][3]);
            }
        }
    } else {
        // ---------------- producer ----------------
        const int pt = t - 128;
        int d = 0, kc = 0;
        for (int c = 0; c < 97; ++c) {
            const int buf = c & 1;
            const uint32_t base = sb + buf * BUFSZ;
            char* baseP = smem + buf * BUFSZ;
            if (c >= 2) bar_sync(BAR_EMPTY + buf);
            // B tiles: cp.async rows of precomputed split W (thread -> one row)
            {
                const int r = pt;   // 0..127: 0-63 hi rows, 64-127 lo rows
                const __nv_bfloat16* src;
                uint32_t dst;
                if (r < 64) {
                    src = g_WsHi + (size_t)c * 4608 + r * 72;
                    dst = base + OB_BH + (uint32_t)r * TSTR;
                } else {
                    src = g_WsLo + (size_t)c * 4608 + (r - 64) * 72;
                    dst = base + OB_BL + (uint32_t)(r - 64) * TSTR;
                }
                #pragma unroll
                for (int q = 0; q < 9; ++q)
                    cp16(dst + q * 16, src + q * 8);
                CP_COMMIT();
            }
            // A tile: A[n][j] = STE[n,d] * h[n][kc*64+j]  (thread -> one row n)
            {
                const int n = pt;
                char* hp = baseP + n * TSTR;
                char* lp = baseP + OB_AL + n * TSTR;
                if (c < 96) {
                    const float s = sT[d * 128 + n];
                    const float* hr = hT + (size_t)(kc * 64) * HT_STR + n;
                    #pragma unroll
                    for (int j = 0; j < 32; ++j) {
                        const float p0 = s * hr[(2 * j)     * HT_STR];
                        const float p1 = s * hr[(2 * j + 1) * HT_STR];
                        uint32_t uh, ul;
                        split2(p0, p1, uh, ul);
                        *reinterpret_cast<uint32_t*>(hp + 4 * j) = uh;
                        *reinterpret_cast<uint32_t*>(lp + 4 * j) = ul;
                    }
                } else {
                    // bias chunk: A[n][j] = STE[n][j], j < 32 (K=32)
                    #pragma unroll
                    for (int j = 0; j < 16; ++j) {
                        const float p0 = sT[(2 * j)     * 128 + n];
                        const float p1 = sT[(2 * j + 1) * 128 + n];
                        uint32_t uh, ul;
                        split2(p0, p1, uh, ul);
                        *reinterpret_cast<uint32_t*>(hp + 4 * j) = uh;
                        *reinterpret_cast<uint32_t*>(lp + 4 * j) = ul;
                    }
                }
            }
            CP_WAIT0();
            bar_arrive(BAR_FULL + buf);
            if (++kc == 3) { kc = 0; ++d; }
        }
    }
}

// ===========================================================================
// Launch. Inputs: x, STE, R, SC, weights_pool, bias_pool.
// ===========================================================================
extern "C" void kernel_launch(void* const* d_in, const int* in_sizes, int n_in,
                              void* d_out, int out_size)
{
    (void)in_sizes; (void)n_in; (void)out_size;
    const float* x     = (const float*)d_in[0];
    const float* STE   = (const float*)d_in[1];
    const float* R     = (const float*)d_in[2];
    const float* SC    = (const float*)d_in[3];
    const float* Wp    = (const float*)d_in[4];
    const float* biasp = (const float*)d_in[5];
    float* out = (float*)d_out;

    cudaFuncSetAttribute(prop_mma<0>, cudaFuncAttributeMaxDynamicSharedMemorySize, P_SMEM);
    cudaFuncSetAttribute(prop_mma<1>, cudaFuncAttributeMaxDynamicSharedMemorySize, P_SMEM);
    cudaFuncSetAttribute(fused_mma,   cudaFuncAttributeMaxDynamicSharedMemorySize, F_SMEM);

    prep_w<<<97, 256>>>(Wp, biasp);
    prop_mma<0><<<dim3(NN / 128, NB, 2), 256, P_SMEM>>>(R, SC, x);
    prop_mma<1><<<dim3(NN / 128, NB, 1), 256, P_SMEM>>>(R, SC, x);
    fused_mma<<<dim3(NN / 128, NB), 256, F_SMEM>>>(STE, out);
}

// round 7
// speedup vs baseline: 2.3714x; 1.3537x over previous
#include <cuda_runtime.h>
#include <cuda_bf16.h>
#include <cstdint>
#include <cstddef>

// Problem constants
#define NB    32
#define NN    512
#define DIN_  64
#define DOUT_ 64
#define ET_   32
#define CHEB  3
#define KI_   (CHEB * DIN_)   // 192

// Scratch: h[b][k][n][i]  fp32 (12.6 MB)
__device__ float g_h[(size_t)NB * CHEB * NN * DIN_];
// Pre-split W (+bias as chunk 96): [97 chunks][64 rows][72 cols] bf16 (144B rows)
__device__ __align__(16) __nv_bfloat16 g_WsHi[97 * 64 * 72];
__device__ __align__(16) __nv_bfloat16 g_WsLo[97 * 64 * 72];

#define TSTR 144u   // B tile row stride bytes (odd multiple of 16B)

// ===========================================================================
// PTX helpers
// ===========================================================================
__device__ __forceinline__ uint32_t smem_u32(const void* p) {
    uint32_t a;
    asm("{ .reg .u64 t; cvta.to.shared.u64 t, %1; cvt.u32.u64 %0, t; }"
        : "=r"(a) : "l"(p));
    return a;
}
__device__ __forceinline__ void ldsm_x4(uint32_t& r0, uint32_t& r1,
                                        uint32_t& r2, uint32_t& r3, uint32_t addr) {
    asm volatile("ldmatrix.sync.aligned.m8n8.x4.shared.b16 {%0,%1,%2,%3}, [%4];"
                 : "=r"(r0), "=r"(r1), "=r"(r2), "=r"(r3) : "r"(addr));
}
__device__ __forceinline__ void ldsm_x4t(uint32_t& r0, uint32_t& r1,
                                         uint32_t& r2, uint32_t& r3, uint32_t addr) {
    asm volatile("ldmatrix.sync.aligned.m8n8.x4.trans.shared.b16 {%0,%1,%2,%3}, [%4];"
                 : "=r"(r0), "=r"(r1), "=r"(r2), "=r"(r3) : "r"(addr));
}
__device__ __forceinline__ void ldsm_x2t(uint32_t& r0, uint32_t& r1, uint32_t addr) {
    asm volatile("ldmatrix.sync.aligned.m8n8.x2.trans.shared.b16 {%0,%1}, [%2];"
                 : "=r"(r0), "=r"(r1) : "r"(addr));
}
__device__ __forceinline__ void mma_bf16(float* c, const uint32_t* a,
                                         uint32_t b0, uint32_t b1) {
    asm volatile(
        "mma.sync.aligned.m16n8k16.row.col.f32.bf16.bf16.f32 "
        "{%0,%1,%2,%3}, {%4,%5,%6,%7}, {%8,%9}, {%0,%1,%2,%3};"
        : "+f"(c[0]), "+f"(c[1]), "+f"(c[2]), "+f"(c[3])
        : "r"(a[0]), "r"(a[1]), "r"(a[2]), "r"(a[3]), "r"(b0), "r"(b1));
}
__device__ __forceinline__ void cp16(uint32_t dst, const void* src) {
    asm volatile("cp.async.ca.shared.global [%0], [%1], 16;" :: "r"(dst), "l"(src));
}
#define CP_COMMIT() asm volatile("cp.async.commit_group;" ::: "memory")
#define CP_WAIT0()  asm volatile("cp.async.wait_group 0;" ::: "memory")
#define CP_WAIT3()  asm volatile("cp.async.wait_group 3;" ::: "memory")
__device__ __forceinline__ void bar_sync(int id) {
    asm volatile("bar.sync %0, 256;" :: "r"(id) : "memory");
}
__device__ __forceinline__ void bar_arrive(int id) {
    asm volatile("bar.arrive %0, 256;" :: "r"(id) : "memory");
}
#define BAR_FULL  1
#define BAR_EMPTY 3

__device__ __forceinline__ uint32_t pack2(float p0, float p1) {
    uint32_t r;
    asm("cvt.rn.bf16x2.f32 %0, %1, %2;" : "=r"(r) : "f"(p1), "f"(p0));
    return r;
}
__device__ __forceinline__ void split2(float p0, float p1, uint32_t& uh, uint32_t& ul) {
    uh = pack2(p0, p1);
    const float h0 = __uint_as_float(uh << 16);
    const float h1 = __uint_as_float(uh & 0xffff0000u);
    ul = pack2(p0 - h0, p1 - h1);
}

// ===========================================================================
// Precompute: split W (+bias chunk 96) into padded bf16 hi/lo tiles.
// ===========================================================================
__global__ __launch_bounds__(256) void prep_w(const float* __restrict__ Wp,
                                              const float* __restrict__ biasp) {
    const int c = blockIdx.x;
    const int t = threadIdx.x;
    __nv_bfloat16* hi = g_WsHi + (size_t)c * 64 * 72;
    __nv_bfloat16* lo = g_WsLo + (size_t)c * 64 * 72;
    #pragma unroll
    for (int it = 0; it < 4; ++it) {
        const int idx = t + it * 256;
        const int k  = idx >> 4;
        const int o4 = (idx & 15) * 4;
        float4 v = make_float4(0.f, 0.f, 0.f, 0.f);
        if (c < 96) {
            const int d = c / 3, kc = c - d * 3;
            v = *reinterpret_cast<const float4*>(Wp + ((size_t)(d * KI_ + kc * 64 + k)) * DOUT_ + o4);
        } else if (k < 32) {
            v = *reinterpret_cast<const float4*>(biasp + (size_t)k * DOUT_ + o4);
        }
        uint32_t h0, l0, h1, l1;
        split2(v.x, v.y, h0, l0);
        split2(v.z, v.w, h1, l1);
        *reinterpret_cast<uint2*>(hi + k * 72 + o4) = make_uint2(h0, h1);
        *reinterpret_cast<uint2*>(lo + k * 72 + o4) = make_uint2(l0, l1);
    }
    if (t < 64) {
        *reinterpret_cast<uint4*>(hi + t * 72 + 64) = make_uint4(0, 0, 0, 0);
        *reinterpret_cast<uint4*>(lo + t * 72 + 64) = make_uint4(0, 0, 0, 0);
    }
}

// ===========================================================================
// Prop kernels (warp-specialized): C[512x64] = A[512x512] @ Bm[512x64].
// MODE 0: z selects SC->h0 / R->h1, Bm=x.  MODE 1: A=R, Bm=h1, C=2*acc-h0 -> h2
// ===========================================================================
#define BUFSZ   55296
#define OB_AL   18432
#define OB_BH   36864
#define OB_BL   46080
#define P_SMEM  (2 * BUFSZ)

__device__ __forceinline__ void mma_chunk(float acc[2][8][4],
                                          uint32_t aH, uint32_t aL,
                                          uint32_t bH, uint32_t bL,
                                          int warp, int lane, int ksteps) {
    const uint32_t rowSel = (uint32_t)(warp * 32 + (lane & 15));
    const uint32_t kSel   = (uint32_t)((lane >> 4) << 3);
    const uint32_t kSelB  = (uint32_t)(lane & 15);
    for (int ks = 0; ks < ksteps; ++ks) {
        const uint32_t kb = (uint32_t)(ks * 16);
        uint32_t ah[2][4], al[2][4];
        #pragma unroll
        for (int mt = 0; mt < 2; ++mt) {
            const uint32_t off = (rowSel + (uint32_t)(mt * 16)) * TSTR + (kb + kSel) * 2u;
            ldsm_x4(ah[mt][0], ah[mt][1], ah[mt][2], ah[mt][3], aH + off);
            ldsm_x4(al[mt][0], al[mt][1], al[mt][2], al[mt][3], aL + off);
        }
        #pragma unroll
        for (int nt = 0; nt < 8; ++nt) {
            const uint32_t off = (kb + kSelB) * TSTR + (uint32_t)(nt * 16);
            uint32_t bh0, bh1, bl0, bl1;
            ldsm_x2t(bh0, bh1, bH + off);
            ldsm_x2t(bl0, bl1, bL + off);
            #pragma unroll
            for (int mt = 0; mt < 2; ++mt) {
                mma_bf16(acc[mt][nt], ah[mt], bh0, bh1);
                mma_bf16(acc[mt][nt], ah[mt], bl0, bl1);
                mma_bf16(acc[mt][nt], al[mt], bh0, bh1);
            }
        }
    }
}

template<int MODE>
__global__ __launch_bounds__(256, 1) void prop_mma(
    const float* __restrict__ R,
    const float* __restrict__ SC,
    const float* __restrict__ X)
{
    extern __shared__ char smem[];
    const int b = blockIdx.y;
    const int rowBlk = blockIdx.x * 128;

    float* hb = g_h + (size_t)b * (CHEB * NN * DIN_);
    const float* A;
    const float* Bm;
    const float* Sub = nullptr;
    float* C;
    if (MODE == 0) {
        const int which = blockIdx.z;
        A  = (which == 0 ? SC : R) + (size_t)b * NN * NN;
        Bm = X + (size_t)b * NN * DIN_;
        C  = hb + (size_t)which * NN * DIN_;
    } else {
        A   = R  + (size_t)b * NN * NN;
        Bm  = hb + (size_t)1 * NN * DIN_;
        Sub = hb + (size_t)0 * NN * DIN_;
        C   = hb + (size_t)2 * NN * DIN_;
    }

    const int t    = threadIdx.x;
    const int wid  = t >> 5;
    const int lane = t & 31;
    const uint32_t sb = smem_u32(smem);

    if (wid < 4) {
        float acc[2][8][4];
        #pragma unroll
        for (int mt = 0; mt < 2; ++mt)
            #pragma unroll
            for (int nt = 0; nt < 8; ++nt)
                #pragma unroll
                for (int e = 0; e < 4; ++e) acc[mt][nt][e] = 0.f;

        for (int c = 0; c < 8; ++c) {
            const int buf = c & 1;
            const uint32_t base = sb + buf * BUFSZ;
            bar_sync(BAR_FULL + buf);
            mma_chunk(acc, base, base + OB_AL, base + OB_BH, base + OB_BL, wid, lane, 4);
            bar_arrive(BAR_EMPTY + buf);
        }
        const int r0   = rowBlk + wid * 32 + (lane >> 2);
        const int col0 = 2 * (lane & 3);
        #pragma unroll
        for (int mt = 0; mt < 2; ++mt) {
            #pragma unroll
            for (int nt = 0; nt < 8; ++nt) {
                const int row = r0 + mt * 16;
                const int cc  = col0 + nt * 8;
                float2 v0, v1;
                if (MODE == 1) {
                    const float2 s0 = *reinterpret_cast<const float2*>(Sub + (size_t)row * DIN_ + cc);
                    const float2 s1 = *reinterpret_cast<const float2*>(Sub + (size_t)(row + 8) * DIN_ + cc);
                    v0 = make_float2(2.f * acc[mt][nt][0] - s0.x, 2.f * acc[mt][nt][1] - s0.y);
                    v1 = make_float2(2.f * acc[mt][nt][2] - s1.x, 2.f * acc[mt][nt][3] - s1.y);
                } else {
                    v0 = make_float2(acc[mt][nt][0], acc[mt][nt][1]);
                    v1 = make_float2(acc[mt][nt][2], acc[mt][nt][3]);
                }
                *reinterpret_cast<float2*>(C + (size_t)row * DIN_ + cc)       = v0;
                *reinterpret_cast<float2*>(C + (size_t)(row + 8) * DIN_ + cc) = v1;
            }
        }
    } else {
        const int pt = t - 128;
        for (int c = 0; c < 8; ++c) {
            const int buf = c & 1;
            char* baseP = smem + buf * BUFSZ;
            if (c >= 2) bar_sync(BAR_EMPTY + buf);
            #pragma unroll
            for (int q = 0; q < 16; ++q) {
                const int idx = pt + q * 128;
                const int n  = idx >> 4;
                const int j4 = (idx & 15) * 4;
                const float4 v = *reinterpret_cast<const float4*>(
                    A + (size_t)(rowBlk + n) * NN + c * 64 + j4);
                uint32_t h0, l0, h1, l1;
                split2(v.x, v.y, h0, l0);
                split2(v.z, v.w, h1, l1);
                *reinterpret_cast<uint2*>(baseP + n * TSTR + j4 * 2)         = make_uint2(h0, h1);
                *reinterpret_cast<uint2*>(baseP + OB_AL + n * TSTR + j4 * 2) = make_uint2(l0, l1);
            }
            #pragma unroll
            for (int q = 0; q < 8; ++q) {
                const int idx = pt + q * 128;
                const int k  = idx >> 4;
                const int i4 = (idx & 15) * 4;
                const float4 v = *reinterpret_cast<const float4*>(
                    Bm + (size_t)(c * 64 + k) * DIN_ + i4);
                uint32_t h0, l0, h1, l1;
                split2(v.x, v.y, h0, l0);
                split2(v.z, v.w, h1, l1);
                *reinterpret_cast<uint2*>(baseP + OB_BH + k * TSTR + i4 * 2) = make_uint2(h0, h1);
                *reinterpret_cast<uint2*>(baseP + OB_BL + k * TSTR + i4 * 2) = make_uint2(l0, l1);
            }
            bar_arrive(BAR_FULL + buf);
        }
    }
}

// ===========================================================================
// Fused contraction, all-consumer version.
// fin[n,o] = sum_d STE[n,d] * (h @ W[d])[n,o] + (STE @ bias)[n,o]
// A (h hi/lo + STE hi/lo as cols 192..223) built ONCE, resident in smem.
// B tiles stream via 4-deep cp.async pipeline from pre-split g_Ws.
// All 8 warps compute (2x4 grid, 32x32 tiles). Scale fold in registers.
// smem: AH 59392 | AL 59392 | sT 16384 | B 4x18432  = 208896 B
// ===========================================================================
#define DEPTH    4
#define A_STR    464u
#define OFF_AL2  59392
#define OFF_ST2  118784
#define OFF_B2   135168
#define BSLOT    18432
#define F_SMEM   208896

__global__ __launch_bounds__(256, 1) void fused_mma(
    const float* __restrict__ STE,
    float* __restrict__ out)
{
    extern __shared__ char smem[];
    const int b     = blockIdx.y;
    const int nBase = blockIdx.x * 128;
    const int t    = threadIdx.x;
    const int wid  = t >> 5;
    const int lane = t & 31;
    const int wy   = wid & 3;      // row group (4)
    const int wx   = wid >> 2;     // col group (2)
    const uint32_t sb = smem_u32(smem);
    float* sT = reinterpret_cast<float*>(smem + OFF_ST2);

    // ---- Build static A: h split (cols 0..191) + STE split (cols 192..223) ----
    {
        const float* hsrc = g_h + (size_t)b * (CHEB * NN * DIN_);
        #pragma unroll
        for (int it = 0; it < 24; ++it) {
            const int idx = t + it * 256;          // 0..6143 float4s
            const int i4 = (idx & 15) * 4;
            const int n  = (idx >> 4) & 127;
            const int k  = idx >> 11;
            const float4 v = *reinterpret_cast<const float4*>(
                hsrc + ((size_t)k * NN + nBase + n) * DIN_ + i4);
            uint32_t h0, l0, h1, l1;
            split2(v.x, v.y, h0, l0);
            split2(v.z, v.w, h1, l1);
            const uint32_t boff = (uint32_t)n * A_STR + (uint32_t)(k * 64 + i4) * 2u;
            *reinterpret_cast<uint2*>(smem + boff)            = make_uint2(h0, h1);
            *reinterpret_cast<uint2*>(smem + OFF_AL2 + boff)  = make_uint2(l0, l1);
        }
        const float* ssrc = STE + ((size_t)b * NN + nBase) * ET_;
        #pragma unroll
        for (int it = 0; it < 4; ++it) {
            const int idx = t + it * 256;          // 0..1023 float4s
            const int d4 = (idx & 7) * 4;
            const int n  = idx >> 3;
            const float4 v = *reinterpret_cast<const float4*>(ssrc + n * ET_ + d4);
            uint32_t h0, l0, h1, l1;
            split2(v.x, v.y, h0, l0);
            split2(v.z, v.w, h1, l1);
            const uint32_t boff = (uint32_t)n * A_STR + (uint32_t)(192 + d4) * 2u;
            *reinterpret_cast<uint2*>(smem + boff)           = make_uint2(h0, h1);
            *reinterpret_cast<uint2*>(smem + OFF_AL2 + boff) = make_uint2(l0, l1);
            sT[(d4 + 0) * 128 + n] = v.x;
            sT[(d4 + 1) * 128 + n] = v.y;
            sT[(d4 + 2) * 128 + n] = v.z;
            sT[(d4 + 3) * 128 + n] = v.w;
        }
    }

    // ---- B tile loader: 1152 cp16 per chunk spread over 256 threads ----
    auto load_b = [&](int c, int slot) {
        const uint32_t sbase = sb + OFF_B2 + (uint32_t)slot * BSLOT;
        auto emit = [&](int idx) {
            const int r  = idx / 9;
            const int q9 = idx - r * 9;
            const int rr = r & 63;
            const __nv_bfloat16* src =
                ((r < 64) ? g_WsHi : g_WsLo) + (size_t)c * 4608 + rr * 72 + q9 * 8;
            const uint32_t dst = sbase + ((r < 64) ? 0u : 9216u)
                               + (uint32_t)rr * TSTR + (uint32_t)q9 * 16u;
            cp16(dst, src);
        };
        #pragma unroll
        for (int q = 0; q < 4; ++q) emit(t + q * 256);
        if (t < 128) emit(1024 + t);
    };

    // Prologue: fill pipeline
    #pragma unroll
    for (int s = 0; s < DEPTH; ++s) { load_b(s, s); CP_COMMIT(); }

    float fin[2][4][4];
    float part[2][4][4];
    #pragma unroll
    for (int mt = 0; mt < 2; ++mt)
        #pragma unroll
        for (int nt = 0; nt < 4; ++nt)
            #pragma unroll
            for (int e = 0; e < 4; ++e) fin[mt][nt][e] = 0.f;

    const uint32_t rowSel  = (uint32_t)(wy * 32 + (lane & 15));
    const uint32_t kSel    = (uint32_t)((lane >> 4) << 3);
    const uint32_t bRow    = (uint32_t)((lane & 7) + (((lane >> 3) & 1) << 3));
    const uint32_t bColOff = (uint32_t)((wx * 32 + ((lane >> 4) << 3)) * 2);
    const int rl0 = wy * 32 + (lane >> 2);

    int d = 0, kc = 0;
    for (int c = 0; c < 97; ++c) {
        CP_WAIT3();
        __syncthreads();                       // tile c visible to all
        const uint32_t bbase = sb + OFF_B2 + (uint32_t)(c & 3) * BSLOT;
        const int aoff   = (c < 96) ? kc * 64 : 192;
        const int ksteps = (c == 96) ? 2 : 4;

        if (kc == 0) {
            #pragma unroll
            for (int mt = 0; mt < 2; ++mt)
                #pragma unroll
                for (int nt = 0; nt < 4; ++nt)
                    #pragma unroll
                    for (int e = 0; e < 4; ++e) part[mt][nt][e] = 0.f;
        }

        for (int ks = 0; ks < ksteps; ++ks) {
            const uint32_t kb = (uint32_t)(ks * 16);
            uint32_t ah[2][4], al[2][4];
            #pragma unroll
            for (int mt = 0; mt < 2; ++mt) {
                const uint32_t off = (rowSel + (uint32_t)(mt * 16)) * A_STR
                                   + (uint32_t)(aoff + kb + kSel) * 2u;
                ldsm_x4(ah[mt][0], ah[mt][1], ah[mt][2], ah[mt][3], sb + off);
                ldsm_x4(al[mt][0], al[mt][1], al[mt][2], al[mt][3], sb + OFF_AL2 + off);
            }
            #pragma unroll
            for (int ntp = 0; ntp < 2; ++ntp) {
                const uint32_t boff = (kb + bRow) * TSTR + bColOff + (uint32_t)(ntp * 32);
                uint32_t bh0, bh1, bh2, bh3, bl0, bl1, bl2, bl3;
                ldsm_x4t(bh0, bh1, bh2, bh3, bbase + boff);
                ldsm_x4t(bl0, bl1, bl2, bl3, bbase + 9216u + boff);
                #pragma unroll
                for (int mt = 0; mt < 2; ++mt) {
                    mma_bf16(part[mt][2 * ntp],     ah[mt], bh0, bh1);
                    mma_bf16(part[mt][2 * ntp],     ah[mt], bl0, bl1);
                    mma_bf16(part[mt][2 * ntp],     al[mt], bh0, bh1);
                    mma_bf16(part[mt][2 * ntp + 1], ah[mt], bh2, bh3);
                    mma_bf16(part[mt][2 * ntp + 1], ah[mt], bl2, bl3);
                    mma_bf16(part[mt][2 * ntp + 1], al[mt], bh2, bh3);
                }
            }
        }
        __syncthreads();                       // all warps done with slot
        if (c + DEPTH <= 96) load_b(c + DEPTH, (c + DEPTH) & 3);
        CP_COMMIT();                           // keep group count aligned

        if (c == 96) {
            #pragma unroll
            for (int mt = 0; mt < 2; ++mt)
                #pragma unroll
                for (int nt = 0; nt < 4; ++nt)
                    #pragma unroll
                    for (int e = 0; e < 4; ++e) fin[mt][nt][e] += part[mt][nt][e];
        } else if (kc == 2) {
            #pragma unroll
            for (int mt = 0; mt < 2; ++mt) {
                const float s0 = sT[d * 128 + rl0 + mt * 16];
                const float s1 = sT[d * 128 + rl0 + mt * 16 + 8];
                #pragma unroll
                for (int nt = 0; nt < 4; ++nt) {
                    fin[mt][nt][0] += s0 * part[mt][nt][0];
                    fin[mt][nt][1] += s0 * part[mt][nt][1];
                    fin[mt][nt][2] += s1 * part[mt][nt][2];
                    fin[mt][nt][3] += s1 * part[mt][nt][3];
                }
            }
        }
        if (c < 96) { if (++kc == 3) { kc = 0; ++d; } }
    }

    // Epilogue
    const int r0   = nBase + rl0;
    const int col0 = wx * 32 + 2 * (lane & 3);
    float* ob = out + (size_t)b * NN * DOUT_;
    #pragma unroll
    for (int mt = 0; mt < 2; ++mt) {
        #pragma unroll
        for (int nt = 0; nt < 4; ++nt) {
            const int row = r0 + mt * 16;
            const int cc  = col0 + nt * 8;
            *reinterpret_cast<float2*>(ob + (size_t)row * DOUT_ + cc) =
                make_float2(fin[mt][nt][0], fin[mt][nt][1]);
            *reinterpret_cast<float2*>(ob + (size_t)(row + 8) * DOUT_ + cc) =
                make_float2(fin[mt][nt][2], fin[mt][nt][3]);
        }
    }
}

// ===========================================================================
// Launch. Inputs: x, STE, R, SC, weights_pool, bias_pool.
// ===========================================================================
extern "C" void kernel_launch(void* const* d_in, const int* in_sizes, int n_in,
                              void* d_out, int out_size)
{
    (void)in_sizes; (void)n_in; (void)out_size;
    const float* x     = (const float*)d_in[0];
    const float* STE   = (const float*)d_in[1];
    const float* R     = (const float*)d_in[2];
    const float* SC    = (const float*)d_in[3];
    const float* Wp    = (const float*)d_in[4];
    const float* biasp = (const float*)d_in[5];
    float* out = (float*)d_out;

    cudaFuncSetAttribute(prop_mma<0>, cudaFuncAttributeMaxDynamicSharedMemorySize, P_SMEM);
    cudaFuncSetAttribute(prop_mma<1>, cudaFuncAttributeMaxDynamicSharedMemorySize, P_SMEM);
    cudaFuncSetAttribute(fused_mma,   cudaFuncAttributeMaxDynamicSharedMemorySize, F_SMEM);

    prep_w<<<97, 256>>>(Wp, biasp);
    prop_mma<0><<<dim3(NN / 128, NB, 2), 256, P_SMEM>>>(R, SC, x);
    prop_mma<1><<<dim3(NN / 128, NB, 1), 256, P_SMEM>>>(R, SC, x);
    fused_mma<<<dim3(NN / 128, NB), 256, F_SMEM>>>(STE, out);
}

// round 8
// speedup vs baseline: 2.5955x; 1.0945x over previous
#include <cuda_runtime.h>
#include <cuda_bf16.h>
#include <cstdint>
#include <cstddef>

// Problem constants
#define NB    32
#define NN    512
#define DIN_  64
#define DOUT_ 64
#define ET_   32
#define CHEB  3
#define KI_   (CHEB * DIN_)   // 192

// Scratch: h[b][k][n][i]  fp32 (12.6 MB)
__device__ float g_h[(size_t)NB * CHEB * NN * DIN_];
// Pre-split W (+bias as chunk 96), KC-MAJOR order: c = kc*32 + d, bias at 96.
// [97 chunks][64 rows][72 cols] bf16 (144B rows)
__device__ __align__(16) __nv_bfloat16 g_WsHi[97 * 64 * 72];
__device__ __align__(16) __nv_bfloat16 g_WsLo[97 * 64 * 72];

#define TSTR 144u   // B tile row stride bytes (odd multiple of 16B)

// ===========================================================================
// PTX helpers
// ===========================================================================
__device__ __forceinline__ uint32_t smem_u32(const void* p) {
    uint32_t a;
    asm("{ .reg .u64 t; cvta.to.shared.u64 t, %1; cvt.u32.u64 %0, t; }"
        : "=r"(a) : "l"(p));
    return a;
}
__device__ __forceinline__ void ldsm_x4(uint32_t& r0, uint32_t& r1,
                                        uint32_t& r2, uint32_t& r3, uint32_t addr) {
    asm volatile("ldmatrix.sync.aligned.m8n8.x4.shared.b16 {%0,%1,%2,%3}, [%4];"
                 : "=r"(r0), "=r"(r1), "=r"(r2), "=r"(r3) : "r"(addr));
}
__device__ __forceinline__ void ldsm_x4t(uint32_t& r0, uint32_t& r1,
                                         uint32_t& r2, uint32_t& r3, uint32_t addr) {
    asm volatile("ldmatrix.sync.aligned.m8n8.x4.trans.shared.b16 {%0,%1,%2,%3}, [%4];"
                 : "=r"(r0), "=r"(r1), "=r"(r2), "=r"(r3) : "r"(addr));
}
__device__ __forceinline__ void ldsm_x2t(uint32_t& r0, uint32_t& r1, uint32_t addr) {
    asm volatile("ldmatrix.sync.aligned.m8n8.x2.trans.shared.b16 {%0,%1}, [%2];"
                 : "=r"(r0), "=r"(r1) : "r"(addr));
}
__device__ __forceinline__ void mma_bf16(float* c, const uint32_t* a,
                                         uint32_t b0, uint32_t b1) {
    asm volatile(
        "mma.sync.aligned.m16n8k16.row.col.f32.bf16.bf16.f32 "
        "{%0,%1,%2,%3}, {%4,%5,%6,%7}, {%8,%9}, {%0,%1,%2,%3};"
        : "+f"(c[0]), "+f"(c[1]), "+f"(c[2]), "+f"(c[3])
        : "r"(a[0]), "r"(a[1]), "r"(a[2]), "r"(a[3]), "r"(b0), "r"(b1));
}
__device__ __forceinline__ void cp16(uint32_t dst, const void* src) {
    asm volatile("cp.async.ca.shared.global [%0], [%1], 16;" :: "r"(dst), "l"(src));
}
#define CP_COMMIT() asm volatile("cp.async.commit_group;" ::: "memory")
#define CP_WAIT0()  asm volatile("cp.async.wait_group 0;" ::: "memory")
#define CP_WAIT3()  asm volatile("cp.async.wait_group 3;" ::: "memory")
__device__ __forceinline__ void bar_sync(int id) {
    asm volatile("bar.sync %0, 256;" :: "r"(id) : "memory");
}
__device__ __forceinline__ void bar_arrive(int id) {
    asm volatile("bar.arrive %0, 256;" :: "r"(id) : "memory");
}
#define BAR_FULL  1
#define BAR_EMPTY 3

__device__ __forceinline__ uint32_t pack2(float p0, float p1) {
    uint32_t r;
    asm("cvt.rn.bf16x2.f32 %0, %1, %2;" : "=r"(r) : "f"(p1), "f"(p0));
    return r;
}
__device__ __forceinline__ void split2(float p0, float p1, uint32_t& uh, uint32_t& ul) {
    uh = pack2(p0, p1);
    const float h0 = __uint_as_float(uh << 16);
    const float h1 = __uint_as_float(uh & 0xffff0000u);
    ul = pack2(p0 - h0, p1 - h1);
}

// ===========================================================================
// Precompute: split W (+bias chunk 96) into padded bf16 hi/lo tiles.
// Storage order: c = kc*32 + d  (kc-major), bias at c=96.
// ===========================================================================
__global__ __launch_bounds__(256) void prep_w(const float* __restrict__ Wp,
                                              const float* __restrict__ biasp) {
    const int c = blockIdx.x;
    const int t = threadIdx.x;
    __nv_bfloat16* hi = g_WsHi + (size_t)c * 64 * 72;
    __nv_bfloat16* lo = g_WsLo + (size_t)c * 64 * 72;
    #pragma unroll
    for (int it = 0; it < 4; ++it) {
        const int idx = t + it * 256;
        const int k  = idx >> 4;
        const int o4 = (idx & 15) * 4;
        float4 v = make_float4(0.f, 0.f, 0.f, 0.f);
        if (c < 96) {
            const int kc = c >> 5, d = c & 31;
            v = *reinterpret_cast<const float4*>(Wp + ((size_t)(d * KI_ + kc * 64 + k)) * DOUT_ + o4);
        } else if (k < 32) {
            v = *reinterpret_cast<const float4*>(biasp + (size_t)k * DOUT_ + o4);
        }
        uint32_t h0, l0, h1, l1;
        split2(v.x, v.y, h0, l0);
        split2(v.z, v.w, h1, l1);
        *reinterpret_cast<uint2*>(hi + k * 72 + o4) = make_uint2(h0, h1);
        *reinterpret_cast<uint2*>(lo + k * 72 + o4) = make_uint2(l0, l1);
    }
    if (t < 64) {
        *reinterpret_cast<uint4*>(hi + t * 72 + 64) = make_uint4(0, 0, 0, 0);
        *reinterpret_cast<uint4*>(lo + t * 72 + 64) = make_uint4(0, 0, 0, 0);
    }
}

// ===========================================================================
// Prop kernels (warp-specialized, unchanged): C[512x64] = A[512x512] @ Bm[512x64].
// ===========================================================================
#define BUFSZ   55296
#define OB_AL   18432
#define OB_BH   36864
#define OB_BL   46080
#define P_SMEM  (2 * BUFSZ)

__device__ __forceinline__ void mma_chunk(float acc[2][8][4],
                                          uint32_t aH, uint32_t aL,
                                          uint32_t bH, uint32_t bL,
                                          int warp, int lane, int ksteps) {
    const uint32_t rowSel = (uint32_t)(warp * 32 + (lane & 15));
    const uint32_t kSel   = (uint32_t)((lane >> 4) << 3);
    const uint32_t kSelB  = (uint32_t)(lane & 15);
    for (int ks = 0; ks < ksteps; ++ks) {
        const uint32_t kb = (uint32_t)(ks * 16);
        uint32_t ah[2][4], al[2][4];
        #pragma unroll
        for (int mt = 0; mt < 2; ++mt) {
            const uint32_t off = (rowSel + (uint32_t)(mt * 16)) * TSTR + (kb + kSel) * 2u;
            ldsm_x4(ah[mt][0], ah[mt][1], ah[mt][2], ah[mt][3], aH + off);
            ldsm_x4(al[mt][0], al[mt][1], al[mt][2], al[mt][3], aL + off);
        }
        #pragma unroll
        for (int nt = 0; nt < 8; ++nt) {
            const uint32_t off = (kb + kSelB) * TSTR + (uint32_t)(nt * 16);
            uint32_t bh0, bh1, bl0, bl1;
            ldsm_x2t(bh0, bh1, bH + off);
            ldsm_x2t(bl0, bl1, bL + off);
            #pragma unroll
            for (int mt = 0; mt < 2; ++mt) {
                mma_bf16(acc[mt][nt], ah[mt], bh0, bh1);
                mma_bf16(acc[mt][nt], ah[mt], bl0, bl1);
                mma_bf16(acc[mt][nt], al[mt], bh0, bh1);
            }
        }
    }
}

template<int MODE>
__global__ __launch_bounds__(256, 1) void prop_mma(
    const float* __restrict__ R,
    const float* __restrict__ SC,
    const float* __restrict__ X)
{
    extern __shared__ char smem[];
    const int b = blockIdx.y;
    const int rowBlk = blockIdx.x * 128;

    float* hb = g_h + (size_t)b * (CHEB * NN * DIN_);
    const float* A;
    const float* Bm;
    const float* Sub = nullptr;
    float* C;
    if (MODE == 0) {
        const int which = blockIdx.z;
        A  = (which == 0 ? SC : R) + (size_t)b * NN * NN;
        Bm = X + (size_t)b * NN * DIN_;
        C  = hb + (size_t)which * NN * DIN_;
    } else {
        A   = R  + (size_t)b * NN * NN;
        Bm  = hb + (size_t)1 * NN * DIN_;
        Sub = hb + (size_t)0 * NN * DIN_;
        C   = hb + (size_t)2 * NN * DIN_;
    }

    const int t    = threadIdx.x;
    const int wid  = t >> 5;
    const int lane = t & 31;
    const uint32_t sb = smem_u32(smem);

    if (wid < 4) {
        float acc[2][8][4];
        #pragma unroll
        for (int mt = 0; mt < 2; ++mt)
            #pragma unroll
            for (int nt = 0; nt < 8; ++nt)
                #pragma unroll
                for (int e = 0; e < 4; ++e) acc[mt][nt][e] = 0.f;

        for (int c = 0; c < 8; ++c) {
            const int buf = c & 1;
            const uint32_t base = sb + buf * BUFSZ;
            bar_sync(BAR_FULL + buf);
            mma_chunk(acc, base, base + OB_AL, base + OB_BH, base + OB_BL, wid, lane, 4);
            bar_arrive(BAR_EMPTY + buf);
        }
        const int r0   = rowBlk + wid * 32 + (lane >> 2);
        const int col0 = 2 * (lane & 3);
        #pragma unroll
        for (int mt = 0; mt < 2; ++mt) {
            #pragma unroll
            for (int nt = 0; nt < 8; ++nt) {
                const int row = r0 + mt * 16;
                const int cc  = col0 + nt * 8;
                float2 v0, v1;
                if (MODE == 1) {
                    const float2 s0 = *reinterpret_cast<const float2*>(Sub + (size_t)row * DIN_ + cc);
                    const float2 s1 = *reinterpret_cast<const float2*>(Sub + (size_t)(row + 8) * DIN_ + cc);
                    v0 = make_float2(2.f * acc[mt][nt][0] - s0.x, 2.f * acc[mt][nt][1] - s0.y);
                    v1 = make_float2(2.f * acc[mt][nt][2] - s1.x, 2.f * acc[mt][nt][3] - s1.y);
                } else {
                    v0 = make_float2(acc[mt][nt][0], acc[mt][nt][1]);
                    v1 = make_float2(acc[mt][nt][2], acc[mt][nt][3]);
                }
                *reinterpret_cast<float2*>(C + (size_t)row * DIN_ + cc)       = v0;
                *reinterpret_cast<float2*>(C + (size_t)(row + 8) * DIN_ + cc) = v1;
            }
        }
    } else {
        const int pt = t - 128;
        for (int c = 0; c < 8; ++c) {
            const int buf = c & 1;
            char* baseP = smem + buf * BUFSZ;
            if (c >= 2) bar_sync(BAR_EMPTY + buf);
            #pragma unroll
            for (int q = 0; q < 16; ++q) {
                const int idx = pt + q * 128;
                const int n  = idx >> 4;
                const int j4 = (idx & 15) * 4;
                const float4 v = *reinterpret_cast<const float4*>(
                    A + (size_t)(rowBlk + n) * NN + c * 64 + j4);
                uint32_t h0, l0, h1, l1;
                split2(v.x, v.y, h0, l0);
                split2(v.z, v.w, h1, l1);
                *reinterpret_cast<uint2*>(baseP + n * TSTR + j4 * 2)         = make_uint2(h0, h1);
                *reinterpret_cast<uint2*>(baseP + OB_AL + n * TSTR + j4 * 2) = make_uint2(l0, l1);
            }
            #pragma unroll
            for (int q = 0; q < 8; ++q) {
                const int idx = pt + q * 128;
                const int k  = idx >> 4;
                const int i4 = (idx & 15) * 4;
                const float4 v = *reinterpret_cast<const float4*>(
                    Bm + (size_t)(c * 64 + k) * DIN_ + i4);
                uint32_t h0, l0, h1, l1;
                split2(v.x, v.y, h0, l0);
                split2(v.z, v.w, h1, l1);
                *reinterpret_cast<uint2*>(baseP + OB_BH + k * TSTR + i4 * 2) = make_uint2(h0, h1);
                *reinterpret_cast<uint2*>(baseP + OB_BL + k * TSTR + i4 * 2) = make_uint2(l0, l1);
            }
            bar_arrive(BAR_FULL + buf);
        }
    }
}

// ===========================================================================
// Fused contraction, 512 threads, A-hi fragments cached in registers per kc.
// Chunk order: c = kc*32 + d (matches prep_w storage); bias chunk 96.
// Warp grid 4x4: wy rows (32 each), wx cols (16 each).
// smem: AH 59392 | AL 59392 | sT 16384 | B 5x18432 = 227328 B
// ===========================================================================
#define NSLOT    5
#define A_STR    464u
#define OFF_AL2  59392
#define OFF_ST2  118784
#define OFF_B2   135168
#define BSLOT    18432
#define F_SMEM   227328

__global__ __launch_bounds__(512, 1) void fused_mma(
    const float* __restrict__ STE,
    float* __restrict__ out)
{
    extern __shared__ char smem[];
    const int b     = blockIdx.y;
    const int nBase = blockIdx.x * 128;
    const int t    = threadIdx.x;
    const int wid  = t >> 5;
    const int lane = t & 31;
    const int wy   = wid & 3;      // row group (4 x 32 rows)
    const int wx   = wid >> 2;     // col group (4 x 16 cols)
    const uint32_t sb = smem_u32(smem);
    float* sT = reinterpret_cast<float*>(smem + OFF_ST2);

    // ---- Build static A: h split (cols 0..191) + STE split (cols 192..223) ----
    {
        const float* hsrc = g_h + (size_t)b * (CHEB * NN * DIN_);
        #pragma unroll
        for (int it = 0; it < 12; ++it) {
            const int idx = t + it * 512;          // 0..6143 float4s
            const int i4 = (idx & 15) * 4;
            const int n  = (idx >> 4) & 127;
            const int k  = idx >> 11;
            const float4 v = *reinterpret_cast<const float4*>(
                hsrc + ((size_t)k * NN + nBase + n) * DIN_ + i4);
            uint32_t h0, l0, h1, l1;
            split2(v.x, v.y, h0, l0);
            split2(v.z, v.w, h1, l1);
            const uint32_t boff = (uint32_t)n * A_STR + (uint32_t)(k * 64 + i4) * 2u;
            *reinterpret_cast<uint2*>(smem + boff)            = make_uint2(h0, h1);
            *reinterpret_cast<uint2*>(smem + OFF_AL2 + boff)  = make_uint2(l0, l1);
        }
        const float* ssrc = STE + ((size_t)b * NN + nBase) * ET_;
        #pragma unroll
        for (int it = 0; it < 2; ++it) {
            const int idx = t + it * 512;          // 0..1023 float4s
            const int d4 = (idx & 7) * 4;
            const int n  = idx >> 3;
            const float4 v = *reinterpret_cast<const float4*>(ssrc + n * ET_ + d4);
            uint32_t h0, l0, h1, l1;
            split2(v.x, v.y, h0, l0);
            split2(v.z, v.w, h1, l1);
            const uint32_t boff = (uint32_t)n * A_STR + (uint32_t)(192 + d4) * 2u;
            *reinterpret_cast<uint2*>(smem + boff)           = make_uint2(h0, h1);
            *reinterpret_cast<uint2*>(smem + OFF_AL2 + boff) = make_uint2(l0, l1);
            sT[(d4 + 0) * 128 + n] = v.x;
            sT[(d4 + 1) * 128 + n] = v.y;
            sT[(d4 + 2) * 128 + n] = v.z;
            sT[(d4 + 3) * 128 + n] = v.w;
        }
    }

    // ---- B tile loader: 1152 cp16 per chunk spread over 512 threads ----
    auto load_b = [&](int c, int slot) {
        const uint32_t sbase = sb + OFF_B2 + (uint32_t)slot * BSLOT;
        auto emit = [&](int idx) {
            const int r  = idx / 9;
            const int q9 = idx - r * 9;
            const int rr = r & 63;
            const __nv_bfloat16* src =
                ((r < 64) ? g_WsHi : g_WsLo) + (size_t)c * 4608 + rr * 72 + q9 * 8;
            const uint32_t dst = sbase + ((r < 64) ? 0u : 9216u)
                               + (uint32_t)rr * TSTR + (uint32_t)q9 * 16u;
            cp16(dst, src);
        };
        emit(t);
        emit(t + 512);
        if (t < 128) emit(1024 + t);
    };

    // Prologue: fill pipeline (4 groups in flight)
    #pragma unroll
    for (int s = 0; s < 4; ++s) { load_b(s, s); CP_COMMIT(); }

    float fin[2][2][4];
    float part[2][2][4];
    #pragma unroll
    for (int mt = 0; mt < 2; ++mt)
        #pragma unroll
        for (int ng = 0; ng < 2; ++ng)
            #pragma unroll
            for (int e = 0; e < 4; ++e) fin[mt][ng][e] = 0.f;

    const uint32_t rowSel  = (uint32_t)(wy * 32 + (lane & 15));
    const uint32_t kSel    = (uint32_t)((lane >> 4) << 3);
    const uint32_t bRow    = (uint32_t)((lane & 7) + (((lane >> 3) & 1) << 3));
    const uint32_t bColOff = (uint32_t)((wx * 16 + ((lane >> 4) << 3)) * 2);
    const int rl0 = wy * 32 + (lane >> 2);

    uint32_t ahc[4][2][4];   // cached A-hi fragments: [kstep][mt][4]

    for (int c = 0; c < 96; ++c) {
        const int kc = c >> 5;
        const int d  = c & 31;
        CP_WAIT3();
        __syncthreads();                       // tile c landed+visible; c-1 fully consumed
        if (c + 4 <= 96) load_b(c + 4, (c + 4) % NSLOT);
        CP_COMMIT();

        if (d == 0) {   // refresh cached A-hi fragments for this kc
            #pragma unroll
            for (int ks = 0; ks < 4; ++ks)
                #pragma unroll
                for (int mt = 0; mt < 2; ++mt) {
                    const uint32_t off = (rowSel + (uint32_t)(mt * 16)) * A_STR
                                       + (uint32_t)(kc * 64 + ks * 16 + kSel) * 2u;
                    ldsm_x4(ahc[ks][mt][0], ahc[ks][mt][1],
                            ahc[ks][mt][2], ahc[ks][mt][3], sb + off);
                }
        }

        const uint32_t bbase = sb + OFF_B2 + (uint32_t)(c % NSLOT) * BSLOT;
        #pragma unroll
        for (int mt = 0; mt < 2; ++mt)
            #pragma unroll
            for (int ng = 0; ng < 2; ++ng)
                #pragma unroll
                for (int e = 0; e < 4; ++e) part[mt][ng][e] = 0.f;

        #pragma unroll
        for (int ks = 0; ks < 4; ++ks) {
            uint32_t al[2][4];
            #pragma unroll
            for (int mt = 0; mt < 2; ++mt) {
                const uint32_t off = (rowSel + (uint32_t)(mt * 16)) * A_STR
                                   + (uint32_t)(kc * 64 + ks * 16 + kSel) * 2u;
                ldsm_x4(al[mt][0], al[mt][1], al[mt][2], al[mt][3], sb + OFF_AL2 + off);
            }
            const uint32_t boff = ((uint32_t)(ks * 16) + bRow) * TSTR + bColOff;
            uint32_t bh0, bh1, bh2, bh3, bl0, bl1, bl2, bl3;
            ldsm_x4t(bh0, bh1, bh2, bh3, bbase + boff);
            ldsm_x4t(bl0, bl1, bl2, bl3, bbase + 9216u + boff);
            #pragma unroll
            for (int mt = 0; mt < 2; ++mt) {
                mma_bf16(part[mt][0], ahc[ks][mt], bh0, bh1);
                mma_bf16(part[mt][0], ahc[ks][mt], bl0, bl1);
                mma_bf16(part[mt][0], al[mt],      bh0, bh1);
                mma_bf16(part[mt][1], ahc[ks][mt], bh2, bh3);
                mma_bf16(part[mt][1], ahc[ks][mt], bl2, bl3);
                mma_bf16(part[mt][1], al[mt],      bh2, bh3);
            }
        }

        #pragma unroll
        for (int mt = 0; mt < 2; ++mt) {
            const float s0 = sT[d * 128 + rl0 + mt * 16];
            const float s1 = sT[d * 128 + rl0 + mt * 16 + 8];
            #pragma unroll
            for (int ng = 0; ng < 2; ++ng) {
                fin[mt][ng][0] += s0 * part[mt][ng][0];
                fin[mt][ng][1] += s0 * part[mt][ng][1];
                fin[mt][ng][2] += s1 * part[mt][ng][2];
                fin[mt][ng][3] += s1 * part[mt][ng][3];
            }
        }
    }

    // ---- Bias chunk c=96 (K=32, A cols 192..223), accumulated unscaled ----
    {
        CP_WAIT0();
        __syncthreads();
        const uint32_t bbase = sb + OFF_B2 + (uint32_t)(96 % NSLOT) * BSLOT;
        #pragma unroll
        for (int ks = 0; ks < 2; ++ks) {
            uint32_t ah[2][4], al[2][4];
            #pragma unroll
            for (int mt = 0; mt < 2; ++mt) {
                const uint32_t off = (rowSel + (uint32_t)(mt * 16)) * A_STR
                                   + (uint32_t)(192 + ks * 16 + kSel) * 2u;
                ldsm_x4(ah[mt][0], ah[mt][1], ah[mt][2], ah[mt][3], sb + off);
                ldsm_x4(al[mt][0], al[mt][1], al[mt][2], al[mt][3], sb + OFF_AL2 + off);
            }
            const uint32_t boff = ((uint32_t)(ks * 16) + bRow) * TSTR + bColOff;
            uint32_t bh0, bh1, bh2, bh3, bl0, bl1, bl2, bl3;
            ldsm_x4t(bh0, bh1, bh2, bh3, bbase + boff);
            ldsm_x4t(bl0, bl1, bl2, bl3, bbase + 9216u + boff);
            #pragma unroll
            for (int mt = 0; mt < 2; ++mt) {
                mma_bf16(fin[mt][0], ah[mt], bh0, bh1);
                mma_bf16(fin[mt][0], ah[mt], bl0, bl1);
                mma_bf16(fin[mt][0], al[mt], bh0, bh1);
                mma_bf16(fin[mt][1], ah[mt], bh2, bh3);
                mma_bf16(fin[mt][1], ah[mt], bl2, bl3);
                mma_bf16(fin[mt][1], al[mt], bh2, bh3);
            }
        }
    }

    // Epilogue
    const int r0   = nBase + rl0;
    const int col0 = wx * 16 + 2 * (lane & 3);
    float* ob = out + (size_t)b * NN * DOUT_;
    #pragma unroll
    for (int mt = 0; mt < 2; ++mt) {
        #pragma unroll
        for (int ng = 0; ng < 2; ++ng) {
            const int row = r0 + mt * 16;
            const int cc  = col0 + ng * 8;
            *reinterpret_cast<float2*>(ob + (size_t)row * DOUT_ + cc) =
                make_float2(fin[mt][ng][0], fin[mt][ng][1]);
            *reinterpret_cast<float2*>(ob + (size_t)(row + 8) * DOUT_ + cc) =
                make_float2(fin[mt][ng][2], fin[mt][ng][3]);
        }
    }
}

// ===========================================================================
// Launch. Inputs: x, STE, R, SC, weights_pool, bias_pool.
// ===========================================================================
extern "C" void kernel_launch(void* const* d_in, const int* in_sizes, int n_in,
                              void* d_out, int out_size)
{
    (void)in_sizes; (void)n_in; (void)out_size;
    const float* x     = (const float*)d_in[0];
    const float* STE   = (const float*)d_in[1];
    const float* R     = (const float*)d_in[2];
    const float* SC    = (const float*)d_in[3];
    const float* Wp    = (const float*)d_in[4];
    const float* biasp = (const float*)d_in[5];
    float* out = (float*)d_out;

    cudaFuncSetAttribute(prop_mma<0>, cudaFuncAttributeMaxDynamicSharedMemorySize, P_SMEM);
    cudaFuncSetAttribute(prop_mma<1>, cudaFuncAttributeMaxDynamicSharedMemorySize, P_SMEM);
    cudaFuncSetAttribute(fused_mma,   cudaFuncAttributeMaxDynamicSharedMemorySize, F_SMEM);

    prep_w<<<97, 256>>>(Wp, biasp);
    prop_mma<0><<<dim3(NN / 128, NB, 2), 256, P_SMEM>>>(R, SC, x);
    prop_mma<1><<<dim3(NN / 128, NB, 1), 256, P_SMEM>>>(R, SC, x);
    fused_mma<<<dim3(NN / 128, NB), 512, F_SMEM>>>(STE, out);
}

// round 9
// speedup vs baseline: 3.3243x; 1.2808x over previous
#include <cuda_runtime.h>
#include <cuda_bf16.h>
#include <cuda_fp16.h>
#include <cstdint>
#include <cstddef>

// Problem constants
#define NB    32
#define NN    512
#define DIN_  64
#define DOUT_ 64
#define ET_   32
#define CHEB  3
#define KI_   (CHEB * DIN_)   // 192

// Scratch: h[b][k][n][i]  fp32 (12.6 MB)
__device__ float g_h[(size_t)NB * CHEB * NN * DIN_];
// Pre-split W (+bias as chunk 96), KC-MAJOR order: c = kc*32 + d, bias at 96.
// fp16 hi/lo: [97 chunks][64 rows][72 cols] (144B rows)
__device__ __align__(16) __half g_WsHi[97 * 64 * 72];
__device__ __align__(16) __half g_WsLo[97 * 64 * 72];

#define TSTR 144u   // B tile row stride bytes (odd multiple of 16B)

// ===========================================================================
// PTX helpers
// ===========================================================================
__device__ __forceinline__ uint32_t smem_u32(const void* p) {
    uint32_t a;
    asm("{ .reg .u64 t; cvta.to.shared.u64 t, %1; cvt.u32.u64 %0, t; }"
        : "=r"(a) : "l"(p));
    return a;
}
__device__ __forceinline__ void ldsm_x4(uint32_t& r0, uint32_t& r1,
                                        uint32_t& r2, uint32_t& r3, uint32_t addr) {
    asm volatile("ldmatrix.sync.aligned.m8n8.x4.shared.b16 {%0,%1,%2,%3}, [%4];"
                 : "=r"(r0), "=r"(r1), "=r"(r2), "=r"(r3) : "r"(addr));
}
__device__ __forceinline__ void ldsm_x4t(uint32_t& r0, uint32_t& r1,
                                         uint32_t& r2, uint32_t& r3, uint32_t addr) {
    asm volatile("ldmatrix.sync.aligned.m8n8.x4.trans.shared.b16 {%0,%1,%2,%3}, [%4];"
                 : "=r"(r0), "=r"(r1), "=r"(r2), "=r"(r3) : "r"(addr));
}
__device__ __forceinline__ void ldsm_x2t(uint32_t& r0, uint32_t& r1, uint32_t addr) {
    asm volatile("ldmatrix.sync.aligned.m8n8.x2.trans.shared.b16 {%0,%1}, [%2];"
                 : "=r"(r0), "=r"(r1) : "r"(addr));
}
__device__ __forceinline__ void mma_bf16(float* c, const uint32_t* a,
                                         uint32_t b0, uint32_t b1) {
    asm volatile(
        "mma.sync.aligned.m16n8k16.row.col.f32.bf16.bf16.f32 "
        "{%0,%1,%2,%3}, {%4,%5,%6,%7}, {%8,%9}, {%0,%1,%2,%3};"
        : "+f"(c[0]), "+f"(c[1]), "+f"(c[2]), "+f"(c[3])
        : "r"(a[0]), "r"(a[1]), "r"(a[2]), "r"(a[3]), "r"(b0), "r"(b1));
}
__device__ __forceinline__ void mma_fp16(float* c, const uint32_t* a,
                                         uint32_t b0, uint32_t b1) {
    asm volatile(
        "mma.sync.aligned.m16n8k16.row.col.f32.f16.f16.f32 "
        "{%0,%1,%2,%3}, {%4,%5,%6,%7}, {%8,%9}, {%0,%1,%2,%3};"
        : "+f"(c[0]), "+f"(c[1]), "+f"(c[2]), "+f"(c[3])
        : "r"(a[0]), "r"(a[1]), "r"(a[2]), "r"(a[3]), "r"(b0), "r"(b1));
}
__device__ __forceinline__ void cp16(uint32_t dst, const void* src) {
    asm volatile("cp.async.ca.shared.global [%0], [%1], 16;" :: "r"(dst), "l"(src));
}
#define CP_COMMIT() asm volatile("cp.async.commit_group;" ::: "memory")
#define CP_WAIT0()  asm volatile("cp.async.wait_group 0;" ::: "memory")
#define CP_WAIT3()  asm volatile("cp.async.wait_group 3;" ::: "memory")
__device__ __forceinline__ void bar_sync(int id) {
    asm volatile("bar.sync %0, 256;" :: "r"(id) : "memory");
}
__device__ __forceinline__ void bar_arrive(int id) {
    asm volatile("bar.arrive %0, 256;" :: "r"(id) : "memory");
}
#define BAR_FULL  1
#define BAR_EMPTY 3

// bf16 pack/split (prop kernels)
__device__ __forceinline__ uint32_t pack2(float p0, float p1) {
    uint32_t r;
    asm("cvt.rn.bf16x2.f32 %0, %1, %2;" : "=r"(r) : "f"(p1), "f"(p0));
    return r;
}
__device__ __forceinline__ void split2(float p0, float p1, uint32_t& uh, uint32_t& ul) {
    uh = pack2(p0, p1);
    const float h0 = __uint_as_float(uh << 16);
    const float h1 = __uint_as_float(uh & 0xffff0000u);
    ul = pack2(p0 - h0, p1 - h1);
}
// fp16 pack (fused A operand)
__device__ __forceinline__ uint32_t pack2h(float p0, float p1) {
    uint32_t r;
    asm("cvt.rn.f16x2.f32 %0, %1, %2;" : "=r"(r) : "f"(p1), "f"(p0));
    return r;
}

// ===========================================================================
// Precompute: split W (+bias chunk 96) into padded fp16 hi/lo tiles.
// Storage order: c = kc*32 + d (kc-major), bias at c=96.
// ===========================================================================
__global__ __launch_bounds__(256) void prep_w(const float* __restrict__ Wp,
                                              const float* __restrict__ biasp) {
    const int c = blockIdx.x;
    const int t = threadIdx.x;
    __half* hi = g_WsHi + (size_t)c * 64 * 72;
    __half* lo = g_WsLo + (size_t)c * 64 * 72;
    #pragma unroll
    for (int it = 0; it < 4; ++it) {
        const int idx = t + it * 256;
        const int k  = idx >> 4;
        const int o4 = (idx & 15) * 4;
        float4 v = make_float4(0.f, 0.f, 0.f, 0.f);
        if (c < 96) {
            const int kc = c >> 5, d = c & 31;
            v = *reinterpret_cast<const float4*>(Wp + ((size_t)(d * KI_ + kc * 64 + k)) * DOUT_ + o4);
        } else if (k < 32) {
            v = *reinterpret_cast<const float4*>(biasp + (size_t)k * DOUT_ + o4);
        }
        const float vv[4] = {v.x, v.y, v.z, v.w};
        __half hh[4], ll[4];
        #pragma unroll
        for (int e = 0; e < 4; ++e) {
            hh[e] = __float2half_rn(vv[e]);
            ll[e] = __float2half_rn(vv[e] - __half2float(hh[e]));
        }
        *reinterpret_cast<uint2*>(hi + k * 72 + o4) =
            *reinterpret_cast<const uint2*>(hh);
        *reinterpret_cast<uint2*>(lo + k * 72 + o4) =
            *reinterpret_cast<const uint2*>(ll);
    }
    if (t < 64) {
        *reinterpret_cast<uint4*>(hi + t * 72 + 64) = make_uint4(0, 0, 0, 0);
        *reinterpret_cast<uint4*>(lo + t * 72 + 64) = make_uint4(0, 0, 0, 0);
    }
}

// ===========================================================================
// Prop kernels (warp-specialized, bf16 3-split, unchanged):
// C[512x64] = A[512x512] @ Bm[512x64].
// ===========================================================================
#define BUFSZ   55296
#define OB_AL   18432
#define OB_BH   36864
#define OB_BL   46080
#define P_SMEM  (2 * BUFSZ)

__device__ __forceinline__ void mma_chunk(float acc[2][8][4],
                                          uint32_t aH, uint32_t aL,
                                          uint32_t bH, uint32_t bL,
                                          int warp, int lane, int ksteps) {
    const uint32_t rowSel = (uint32_t)(warp * 32 + (lane & 15));
    const uint32_t kSel   = (uint32_t)((lane >> 4) << 3);
    const uint32_t kSelB  = (uint32_t)(lane & 15);
    for (int ks = 0; ks < ksteps; ++ks) {
        const uint32_t kb = (uint32_t)(ks * 16);
        uint32_t ah[2][4], al[2][4];
        #pragma unroll
        for (int mt = 0; mt < 2; ++mt) {
            const uint32_t off = (rowSel + (uint32_t)(mt * 16)) * TSTR + (kb + kSel) * 2u;
            ldsm_x4(ah[mt][0], ah[mt][1], ah[mt][2], ah[mt][3], aH + off);
            ldsm_x4(al[mt][0], al[mt][1], al[mt][2], al[mt][3], aL + off);
        }
        #pragma unroll
        for (int nt = 0; nt < 8; ++nt) {
            const uint32_t off = (kb + kSelB) * TSTR + (uint32_t)(nt * 16);
            uint32_t bh0, bh1, bl0, bl1;
            ldsm_x2t(bh0, bh1, bH + off);
            ldsm_x2t(bl0, bl1, bL + off);
            #pragma unroll
            for (int mt = 0; mt < 2; ++mt) {
                mma_bf16(acc[mt][nt], ah[mt], bh0, bh1);
                mma_bf16(acc[mt][nt], ah[mt], bl0, bl1);
                mma_bf16(acc[mt][nt], al[mt], bh0, bh1);
            }
        }
    }
}

template<int MODE>
__global__ __launch_bounds__(256, 1) void prop_mma(
    const float* __restrict__ R,
    const float* __restrict__ SC,
    const float* __restrict__ X)
{
    extern __shared__ char smem[];
    const int b = blockIdx.y;
    const int rowBlk = blockIdx.x * 128;

    float* hb = g_h + (size_t)b * (CHEB * NN * DIN_);
    const float* A;
    const float* Bm;
    const float* Sub = nullptr;
    float* C;
    if (MODE == 0) {
        const int which = blockIdx.z;
        A  = (which == 0 ? SC : R) + (size_t)b * NN * NN;
        Bm = X + (size_t)b * NN * DIN_;
        C  = hb + (size_t)which * NN * DIN_;
    } else {
        A   = R  + (size_t)b * NN * NN;
        Bm  = hb + (size_t)1 * NN * DIN_;
        Sub = hb + (size_t)0 * NN * DIN_;
        C   = hb + (size_t)2 * NN * DIN_;
    }

    const int t    = threadIdx.x;
    const int wid  = t >> 5;
    const int lane = t & 31;
    const uint32_t sb = smem_u32(smem);

    if (wid < 4) {
        float acc[2][8][4];
        #pragma unroll
        for (int mt = 0; mt < 2; ++mt)
            #pragma unroll
            for (int nt = 0; nt < 8; ++nt)
                #pragma unroll
                for (int e = 0; e < 4; ++e) acc[mt][nt][e] = 0.f;

        for (int c = 0; c < 8; ++c) {
            const int buf = c & 1;
            const uint32_t base = sb + buf * BUFSZ;
            bar_sync(BAR_FULL + buf);
            mma_chunk(acc, base, base + OB_AL, base + OB_BH, base + OB_BL, wid, lane, 4);
            bar_arrive(BAR_EMPTY + buf);
        }
        const int r0   = rowBlk + wid * 32 + (lane >> 2);
        const int col0 = 2 * (lane & 3);
        #pragma unroll
        for (int mt = 0; mt < 2; ++mt) {
            #pragma unroll
            for (int nt = 0; nt < 8; ++nt) {
                const int row = r0 + mt * 16;
                const int cc  = col0 + nt * 8;
                float2 v0, v1;
                if (MODE == 1) {
                    const float2 s0 = *reinterpret_cast<const float2*>(Sub + (size_t)row * DIN_ + cc);
                    const float2 s1 = *reinterpret_cast<const float2*>(Sub + (size_t)(row + 8) * DIN_ + cc);
                    v0 = make_float2(2.f * acc[mt][nt][0] - s0.x, 2.f * acc[mt][nt][1] - s0.y);
                    v1 = make_float2(2.f * acc[mt][nt][2] - s1.x, 2.f * acc[mt][nt][3] - s1.y);
                } else {
                    v0 = make_float2(acc[mt][nt][0], acc[mt][nt][1]);
                    v1 = make_float2(acc[mt][nt][2], acc[mt][nt][3]);
                }
                *reinterpret_cast<float2*>(C + (size_t)row * DIN_ + cc)       = v0;
                *reinterpret_cast<float2*>(C + (size_t)(row + 8) * DIN_ + cc) = v1;
            }
        }
    } else {
        const int pt = t - 128;
        for (int c = 0; c < 8; ++c) {
            const int buf = c & 1;
            char* baseP = smem + buf * BUFSZ;
            if (c >= 2) bar_sync(BAR_EMPTY + buf);
            #pragma unroll
            for (int q = 0; q < 16; ++q) {
                const int idx = pt + q * 128;
                const int n  = idx >> 4;
                const int j4 = (idx & 15) * 4;
                const float4 v = *reinterpret_cast<const float4*>(
                    A + (size_t)(rowBlk + n) * NN + c * 64 + j4);
                uint32_t h0, l0, h1, l1;
                split2(v.x, v.y, h0, l0);
                split2(v.z, v.w, h1, l1);
                *reinterpret_cast<uint2*>(baseP + n * TSTR + j4 * 2)         = make_uint2(h0, h1);
                *reinterpret_cast<uint2*>(baseP + OB_AL + n * TSTR + j4 * 2) = make_uint2(l0, l1);
            }
            #pragma unroll
            for (int q = 0; q < 8; ++q) {
                const int idx = pt + q * 128;
                const int k  = idx >> 4;
                const int i4 = (idx & 15) * 4;
                const float4 v = *reinterpret_cast<const float4*>(
                    Bm + (size_t)(c * 64 + k) * DIN_ + i4);
                uint32_t h0, l0, h1, l1;
                split2(v.x, v.y, h0, l0);
                split2(v.z, v.w, h1, l1);
                *reinterpret_cast<uint2*>(baseP + OB_BH + k * TSTR + i4 * 2) = make_uint2(h0, h1);
                *reinterpret_cast<uint2*>(baseP + OB_BL + k * TSTR + i4 * 2) = make_uint2(l0, l1);
            }
            bar_arrive(BAR_FULL + buf);
        }
    }
}

// ===========================================================================
// Fused contraction, fp16 asymmetric split (A single fp16, B fp16 hi+lo).
// fin[n,o] = sum_d STE[n,d] * (h @ W[d])[n,o] + (STE @ bias)[n,o]
// A (h fp16 cols 0..191 + STE fp16 cols 192..223) built once, resident;
// A fragments register-cached per kc. 512 threads, 4x4 warp grid.
// smem: A 59392 | sT 16384 | B 5x18432 = 167936 B
// ===========================================================================
#define NSLOT    5
#define A_STR    464u
#define OFF_ST2  59392
#define OFF_B2   75776
#define BSLOT    18432
#define F_SMEM   167936

__global__ __launch_bounds__(512, 1) void fused_mma(
    const float* __restrict__ STE,
    float* __restrict__ out)
{
    extern __shared__ char smem[];
    const int b     = blockIdx.y;
    const int nBase = blockIdx.x * 128;
    const int t    = threadIdx.x;
    const int wid  = t >> 5;
    const int lane = t & 31;
    const int wy   = wid & 3;      // row group (4 x 32 rows)
    const int wx   = wid >> 2;     // col group (4 x 16 cols)
    const uint32_t sb = smem_u32(smem);
    float* sT = reinterpret_cast<float*>(smem + OFF_ST2);

    // ---- Build static A (single fp16): h cols 0..191, STE cols 192..223 ----
    {
        const float* hsrc = g_h + (size_t)b * (CHEB * NN * DIN_);
        #pragma unroll
        for (int it = 0; it < 12; ++it) {
            const int idx = t + it * 512;          // 0..6143 float4s
            const int i4 = (idx & 15) * 4;
            const int n  = (idx >> 4) & 127;
            const int k  = idx >> 11;
            const float4 v = *reinterpret_cast<const float4*>(
                hsrc + ((size_t)k * NN + nBase + n) * DIN_ + i4);
            const uint32_t boff = (uint32_t)n * A_STR + (uint32_t)(k * 64 + i4) * 2u;
            *reinterpret_cast<uint2*>(smem + boff) =
                make_uint2(pack2h(v.x, v.y), pack2h(v.z, v.w));
        }
        const float* ssrc = STE + ((size_t)b * NN + nBase) * ET_;
        #pragma unroll
        for (int it = 0; it < 2; ++it) {
            const int idx = t + it * 512;          // 0..1023 float4s
            const int d4 = (idx & 7) * 4;
            const int n  = idx >> 3;
            const float4 v = *reinterpret_cast<const float4*>(ssrc + n * ET_ + d4);
            const uint32_t boff = (uint32_t)n * A_STR + (uint32_t)(192 + d4) * 2u;
            *reinterpret_cast<uint2*>(smem + boff) =
                make_uint2(pack2h(v.x, v.y), pack2h(v.z, v.w));
            sT[(d4 + 0) * 128 + n] = v.x;
            sT[(d4 + 1) * 128 + n] = v.y;
            sT[(d4 + 2) * 128 + n] = v.z;
            sT[(d4 + 3) * 128 + n] = v.w;
        }
    }

    // ---- B tile loader: 1152 cp16 per chunk spread over 512 threads ----
    auto load_b = [&](int c, int slot) {
        const uint32_t sbase = sb + OFF_B2 + (uint32_t)slot * BSLOT;
        auto emit = [&](int idx) {
            const int r  = idx / 9;
            const int q9 = idx - r * 9;
            const int rr = r & 63;
            const __half* src =
                ((r < 64) ? g_WsHi : g_WsLo) + (size_t)c * 4608 + rr * 72 + q9 * 8;
            const uint32_t dst = sbase + ((r < 64) ? 0u : 9216u)
                               + (uint32_t)rr * TSTR + (uint32_t)q9 * 16u;
            cp16(dst, src);
        };
        emit(t);
        emit(t + 512);
        if (t < 128) emit(1024 + t);
    };

    // Prologue: fill pipeline (4 groups in flight)
    #pragma unroll
    for (int s = 0; s < 4; ++s) { load_b(s, s); CP_COMMIT(); }

    float fin[2][2][4];
    float part[2][2][4];
    #pragma unroll
    for (int mt = 0; mt < 2; ++mt)
        #pragma unroll
        for (int ng = 0; ng < 2; ++ng)
            #pragma unroll
            for (int e = 0; e < 4; ++e) fin[mt][ng][e] = 0.f;

    const uint32_t rowSel  = (uint32_t)(wy * 32 + (lane & 15));
    const uint32_t kSel    = (uint32_t)((lane >> 4) << 3);
    const uint32_t bRow    = (uint32_t)((lane & 7) + (((lane >> 3) & 1) << 3));
    const uint32_t bColOff = (uint32_t)((wx * 16 + ((lane >> 4) << 3)) * 2);
    const int rl0 = wy * 32 + (lane >> 2);

    uint32_t ahc[4][2][4];   // cached A fragments (fp16): [kstep][mt][4]

    for (int c = 0; c < 96; ++c) {
        const int kc = c >> 5;
        const int d  = c & 31;
        CP_WAIT3();
        __syncthreads();                       // tile c landed; c-1 fully consumed
        if (c + 4 <= 96) load_b(c + 4, (c + 4) % NSLOT);
        CP_COMMIT();

        if (d == 0) {   // refresh cached A fragments for this kc
            #pragma unroll
            for (int ks = 0; ks < 4; ++ks)
                #pragma unroll
                for (int mt = 0; mt < 2; ++mt) {
                    const uint32_t off = (rowSel + (uint32_t)(mt * 16)) * A_STR
                                       + (uint32_t)(kc * 64 + ks * 16 + kSel) * 2u;
                    ldsm_x4(ahc[ks][mt][0], ahc[ks][mt][1],
                            ahc[ks][mt][2], ahc[ks][mt][3], sb + off);
                }
        }

        const uint32_t bbase = sb + OFF_B2 + (uint32_t)(c % NSLOT) * BSLOT;
        #pragma unroll
        for (int mt = 0; mt < 2; ++mt)
            #pragma unroll
            for (int ng = 0; ng < 2; ++ng)
                #pragma unroll
                for (int e = 0; e < 4; ++e) part[mt][ng][e] = 0.f;

        #pragma unroll
        for (int ks = 0; ks < 4; ++ks) {
            const uint32_t boff = ((uint32_t)(ks * 16) + bRow) * TSTR + bColOff;
            uint32_t bh0, bh1, bh2, bh3, bl0, bl1, bl2, bl3;
            ldsm_x4t(bh0, bh1, bh2, bh3, bbase + boff);
            ldsm_x4t(bl0, bl1, bl2, bl3, bbase + 9216u + boff);
            #pragma unroll
            for (int mt = 0; mt < 2; ++mt) {
                mma_fp16(part[mt][0], ahc[ks][mt], bh0, bh1);
                mma_fp16(part[mt][0], ahc[ks][mt], bl0, bl1);
                mma_fp16(part[mt][1], ahc[ks][mt], bh2, bh3);
                mma_fp16(part[mt][1], ahc[ks][mt], bl2, bl3);
            }
        }

        #pragma unroll
        for (int mt = 0; mt < 2; ++mt) {
            const float s0 = sT[d * 128 + rl0 + mt * 16];
            const float s1 = sT[d * 128 + rl0 + mt * 16 + 8];
            #pragma unroll
            for (int ng = 0; ng < 2; ++ng) {
                fin[mt][ng][0] += s0 * part[mt][ng][0];
                fin[mt][ng][1] += s0 * part[mt][ng][1];
                fin[mt][ng][2] += s1 * part[mt][ng][2];
                fin[mt][ng][3] += s1 * part[mt][ng][3];
            }
        }
    }

    // ---- Bias chunk c=96 (K=32, A cols 192..223), accumulated unscaled ----
    {
        CP_WAIT0();
        __syncthreads();
        const uint32_t bbase = sb + OFF_B2 + (uint32_t)(96 % NSLOT) * BSLOT;
        #pragma unroll
        for (int ks = 0; ks < 2; ++ks) {
            uint32_t ah[2][4];
            #pragma unroll
            for (int mt = 0; mt < 2; ++mt) {
                const uint32_t off = (rowSel + (uint32_t)(mt * 16)) * A_STR
                                   + (uint32_t)(192 + ks * 16 + kSel) * 2u;
                ldsm_x4(ah[mt][0], ah[mt][1], ah[mt][2], ah[mt][3], sb + off);
            }
            const uint32_t boff = ((uint32_t)(ks * 16) + bRow) * TSTR + bColOff;
            uint32_t bh0, bh1, bh2, bh3, bl0, bl1, bl2, bl3;
            ldsm_x4t(bh0, bh1, bh2, bh3, bbase + boff);
            ldsm_x4t(bl0, bl1, bl2, bl3, bbase + 9216u + boff);
            #pragma unroll
            for (int mt = 0; mt < 2; ++mt) {
                mma_fp16(fin[mt][0], ah[mt], bh0, bh1);
                mma_fp16(fin[mt][0], ah[mt], bl0, bl1);
                mma_fp16(fin[mt][1], ah[mt], bh2, bh3);
                mma_fp16(fin[mt][1], ah[mt], bl2, bl3);
            }
        }
    }

    // Epilogue
    const int r0   = nBase + rl0;
    const int col0 = wx * 16 + 2 * (lane & 3);
    float* ob = out + (size_t)b * NN * DOUT_;
    #pragma unroll
    for (int mt = 0; mt < 2; ++mt) {
        #pragma unroll
        for (int ng = 0; ng < 2; ++ng) {
            const int row = r0 + mt * 16;
            const int cc  = col0 + ng * 8;
            *reinterpret_cast<float2*>(ob + (size_t)row * DOUT_ + cc) =
                make_float2(fin[mt][ng][0], fin[mt][ng][1]);
            *reinterpret_cast<float2*>(ob + (size_t)(row + 8) * DOUT_ + cc) =
                make_float2(fin[mt][ng][2], fin[mt][ng][3]);
        }
    }
}

// ===========================================================================
// Launch. Inputs: x, STE, R, SC, weights_pool, bias_pool.
// ===========================================================================
extern "C" void kernel_launch(void* const* d_in, const int* in_sizes, int n_in,
                              void* d_out, int out_size)
{
    (void)in_sizes; (void)n_in; (void)out_size;
    const float* x     = (const float*)d_in[0];
    const float* STE   = (const float*)d_in[1];
    const float* R     = (const float*)d_in[2];
    const float* SC    = (const float*)d_in[3];
    const float* Wp    = (const float*)d_in[4];
    const float* biasp = (const float*)d_in[5];
    float* out = (float*)d_out;

    cudaFuncSetAttribute(prop_mma<0>, cudaFuncAttributeMaxDynamicSharedMemorySize, P_SMEM);
    cudaFuncSetAttribute(prop_mma<1>, cudaFuncAttributeMaxDynamicSharedMemorySize, P_SMEM);
    cudaFuncSetAttribute(fused_mma,   cudaFuncAttributeMaxDynamicSharedMemorySize, F_SMEM);

    prep_w<<<97, 256>>>(Wp, biasp);
    prop_mma<0><<<dim3(NN / 128, NB, 2), 256, P_SMEM>>>(R, SC, x);
    prop_mma<1><<<dim3(NN / 128, NB, 1), 256, P_SMEM>>>(R, SC, x);
    fused_mma<<<dim3(NN / 128, NB), 512, F_SMEM>>>(STE, out);
}

// round 11
// speedup vs baseline: 4.6416x; 1.3963x over previous
#include <cuda_runtime.h>
#include <cuda_bf16.h>
#include <cuda_fp16.h>
#include <cstdint>
#include <cstddef>

// Problem constants
#define NB    32
#define NN    512
#define DIN_  64
#define DOUT_ 64
#define ET_   32
#define CHEB  3
#define KI_   (CHEB * DIN_)   // 192

// Scratch: h[b][k][n][i]  fp32 (12.6 MB)
__device__ float g_h[(size_t)NB * CHEB * NN * DIN_];
// Pre-converted W (+bias as chunk 96), KC-MAJOR: c = kc*32 + d, bias at 96.
// fp16 (single precision level): [97 chunks][64 rows][72 cols] (144B rows)
__device__ __align__(16) __half g_Ws[97 * 64 * 72];

#define TSTR 144u   // B tile row stride bytes (odd multiple of 16B)

// ===========================================================================
// PTX helpers
// ===========================================================================
__device__ __forceinline__ uint32_t smem_u32(const void* p) {
    uint32_t a;
    asm("{ .reg .u64 t; cvta.to.shared.u64 t, %1; cvt.u32.u64 %0, t; }"
        : "=r"(a) : "l"(p));
    return a;
}
__device__ __forceinline__ void ldsm_x4(uint32_t& r0, uint32_t& r1,
                                        uint32_t& r2, uint32_t& r3, uint32_t addr) {
    asm volatile("ldmatrix.sync.aligned.m8n8.x4.shared.b16 {%0,%1,%2,%3}, [%4];"
                 : "=r"(r0), "=r"(r1), "=r"(r2), "=r"(r3) : "r"(addr));
}
__device__ __forceinline__ void ldsm_x4t(uint32_t& r0, uint32_t& r1,
                                         uint32_t& r2, uint32_t& r3, uint32_t addr) {
    asm volatile("ldmatrix.sync.aligned.m8n8.x4.trans.shared.b16 {%0,%1,%2,%3}, [%4];"
                 : "=r"(r0), "=r"(r1), "=r"(r2), "=r"(r3) : "r"(addr));
}
__device__ __forceinline__ void ldsm_x2t(uint32_t& r0, uint32_t& r1, uint32_t addr) {
    asm volatile("ldmatrix.sync.aligned.m8n8.x2.trans.shared.b16 {%0,%1}, [%2];"
                 : "=r"(r0), "=r"(r1) : "r"(addr));
}
__device__ __forceinline__ void mma_bf16(float* c, const uint32_t* a,
                                         uint32_t b0, uint32_t b1) {
    asm volatile(
        "mma.sync.aligned.m16n8k16.row.col.f32.bf16.bf16.f32 "
        "{%0,%1,%2,%3}, {%4,%5,%6,%7}, {%8,%9}, {%0,%1,%2,%3};"
        : "+f"(c[0]), "+f"(c[1]), "+f"(c[2]), "+f"(c[3])
        : "r"(a[0]), "r"(a[1]), "r"(a[2]), "r"(a[3]), "r"(b0), "r"(b1));
}
__device__ __forceinline__ void mma_fp16(float* c, const uint32_t* a,
                                         uint32_t b0, uint32_t b1) {
    asm volatile(
        "mma.sync.aligned.m16n8k16.row.col.f32.f16.f16.f32 "
        "{%0,%1,%2,%3}, {%4,%5,%6,%7}, {%8,%9}, {%0,%1,%2,%3};"
        : "+f"(c[0]), "+f"(c[1]), "+f"(c[2]), "+f"(c[3])
        : "r"(a[0]), "r"(a[1]), "r"(a[2]), "r"(a[3]), "r"(b0), "r"(b1));
}
__device__ __forceinline__ void cp16(uint32_t dst, const void* src) {
    asm volatile("cp.async.ca.shared.global [%0], [%1], 16;" :: "r"(dst), "l"(src));
}
#define CP_COMMIT() asm volatile("cp.async.commit_group;" ::: "memory")
#define CP_WAIT0()  asm volatile("cp.async.wait_group 0;" ::: "memory")
#define CP_WAIT2()  asm volatile("cp.async.wait_group 2;" ::: "memory")
__device__ __forceinline__ void bar_sync(int id) {
    asm volatile("bar.sync %0, 256;" :: "r"(id) : "memory");
}
__device__ __forceinline__ void bar_arrive(int id) {
    asm volatile("bar.arrive %0, 256;" :: "r"(id) : "memory");
}
#define BAR_FULL  1
#define BAR_EMPTY 3

// bf16 pack/split (prop kernels)
__device__ __forceinline__ uint32_t pack2(float p0, float p1) {
    uint32_t r;
    asm("cvt.rn.bf16x2.f32 %0, %1, %2;" : "=r"(r) : "f"(p1), "f"(p0));
    return r;
}
__device__ __forceinline__ void split2(float p0, float p1, uint32_t& uh, uint32_t& ul) {
    uh = pack2(p0, p1);
    const float h0 = __uint_as_float(uh << 16);
    const float h1 = __uint_as_float(uh & 0xffff0000u);
    ul = pack2(p0 - h0, p1 - h1);
}
// fp16 pack (fused A operand)
__device__ __forceinline__ uint32_t pack2h(float p0, float p1) {
    uint32_t r;
    asm("cvt.rn.f16x2.f32 %0, %1, %2;" : "=r"(r) : "f"(p1), "f"(p0));
    return r;
}

// ===========================================================================
// Precompute: convert W (+bias chunk 96) to padded fp16 tiles, kc-major.
// ===========================================================================
__global__ __launch_bounds__(256) void prep_w(const float* __restrict__ Wp,
                                              const float* __restrict__ biasp) {
    const int c = blockIdx.x;
    const int t = threadIdx.x;
    __half* hi = g_Ws + (size_t)c * 64 * 72;
    #pragma unroll
    for (int it = 0; it < 4; ++it) {
        const int idx = t + it * 256;
        const int k  = idx >> 4;
        const int o4 = (idx & 15) * 4;
        float4 v = make_float4(0.f, 0.f, 0.f, 0.f);
        if (c < 96) {
            const int kc = c >> 5, d = c & 31;
            v = *reinterpret_cast<const float4*>(Wp + ((size_t)(d * KI_ + kc * 64 + k)) * DOUT_ + o4);
        } else if (k < 32) {
            v = *reinterpret_cast<const float4*>(biasp + (size_t)k * DOUT_ + o4);
        }
        *reinterpret_cast<uint2*>(hi + k * 72 + o4) =
            make_uint2(pack2h(v.x, v.y), pack2h(v.z, v.w));
    }
    if (t < 64)
        *reinterpret_cast<uint4*>(hi + t * 72 + 64) = make_uint4(0, 0, 0, 0);
}

// ===========================================================================
// Prop kernels (warp-specialized, bf16 3-split, unchanged):
// C[512x64] = A[512x512] @ Bm[512x64].
// ===========================================================================
#define BUFSZ   55296
#define OB_AL   18432
#define OB_BH   36864
#define OB_BL   46080
#define P_SMEM  (2 * BUFSZ)

__device__ __forceinline__ void mma_chunk(float acc[2][8][4],
                                          uint32_t aH, uint32_t aL,
                                          uint32_t bH, uint32_t bL,
                                          int warp, int lane, int ksteps) {
    const uint32_t rowSel = (uint32_t)(warp * 32 + (lane & 15));
    const uint32_t kSel   = (uint32_t)((lane >> 4) << 3);
    const uint32_t kSelB  = (uint32_t)(lane & 15);
    for (int ks = 0; ks < ksteps; ++ks) {
        const uint32_t kb = (uint32_t)(ks * 16);
        uint32_t ah[2][4], al[2][4];
        #pragma unroll
        for (int mt = 0; mt < 2; ++mt) {
            const uint32_t off = (rowSel + (uint32_t)(mt * 16)) * TSTR + (kb + kSel) * 2u;
            ldsm_x4(ah[mt][0], ah[mt][1], ah[mt][2], ah[mt][3], aH + off);
            ldsm_x4(al[mt][0], al[mt][1], al[mt][2], al[mt][3], aL + off);
        }
        #pragma unroll
        for (int nt = 0; nt < 8; ++nt) {
            const uint32_t off = (kb + kSelB) * TSTR + (uint32_t)(nt * 16);
            uint32_t bh0, bh1, bl0, bl1;
            ldsm_x2t(bh0, bh1, bH + off);
            ldsm_x2t(bl0, bl1, bL + off);
            #pragma unroll
            for (int mt = 0; mt < 2; ++mt) {
                mma_bf16(acc[mt][nt], ah[mt], bh0, bh1);
                mma_bf16(acc[mt][nt], ah[mt], bl0, bl1);
                mma_bf16(acc[mt][nt], al[mt], bh0, bh1);
            }
        }
    }
}

template<int MODE>
__global__ __launch_bounds__(256, 1) void prop_mma(
    const float* __restrict__ R,
    const float* __restrict__ SC,
    const float* __restrict__ X)
{
    extern __shared__ char smem[];
    const int b = blockIdx.y;
    const int rowBlk = blockIdx.x * 128;

    float* hb = g_h + (size_t)b * (CHEB * NN * DIN_);
    const float* A;
    const float* Bm;
    const float* Sub = nullptr;
    float* C;
    if (MODE == 0) {
        const int which = blockIdx.z;
        A  = (which == 0 ? SC : R) + (size_t)b * NN * NN;
        Bm = X + (size_t)b * NN * DIN_;
        C  = hb + (size_t)which * NN * DIN_;
    } else {
        A   = R  + (size_t)b * NN * NN;
        Bm  = hb + (size_t)1 * NN * DIN_;
        Sub = hb + (size_t)0 * NN * DIN_;
        C   = hb + (size_t)2 * NN * DIN_;
    }

    const int t    = threadIdx.x;
    const int wid  = t >> 5;
    const int lane = t & 31;
    const uint32_t sb = smem_u32(smem);

    if (wid < 4) {
        float acc[2][8][4];
        #pragma unroll
        for (int mt = 0; mt < 2; ++mt)
            #pragma unroll
            for (int nt = 0; nt < 8; ++nt)
                #pragma unroll
                for (int e = 0; e < 4; ++e) acc[mt][nt][e] = 0.f;

        for (int c = 0; c < 8; ++c) {
            const int buf = c & 1;
            const uint32_t base = sb + buf * BUFSZ;
            bar_sync(BAR_FULL + buf);
            mma_chunk(acc, base, base + OB_AL, base + OB_BH, base + OB_BL, wid, lane, 4);
            bar_arrive(BAR_EMPTY + buf);
        }
        const int r0   = rowBlk + wid * 32 + (lane >> 2);
        const int col0 = 2 * (lane & 3);
        #pragma unroll
        for (int mt = 0; mt < 2; ++mt) {
            #pragma unroll
            for (int nt = 0; nt < 8; ++nt) {
                const int row = r0 + mt * 16;
                const int cc  = col0 + nt * 8;
                float2 v0, v1;
                if (MODE == 1) {
                    const float2 s0 = *reinterpret_cast<const float2*>(Sub + (size_t)row * DIN_ + cc);
                    const float2 s1 = *reinterpret_cast<const float2*>(Sub + (size_t)(row + 8) * DIN_ + cc);
                    v0 = make_float2(2.f * acc[mt][nt][0] - s0.x, 2.f * acc[mt][nt][1] - s0.y);
                    v1 = make_float2(2.f * acc[mt][nt][2] - s1.x, 2.f * acc[mt][nt][3] - s1.y);
                } else {
                    v0 = make_float2(acc[mt][nt][0], acc[mt][nt][1]);
                    v1 = make_float2(acc[mt][nt][2], acc[mt][nt][3]);
                }
                *reinterpret_cast<float2*>(C + (size_t)row * DIN_ + cc)       = v0;
                *reinterpret_cast<float2*>(C + (size_t)(row + 8) * DIN_ + cc) = v1;
            }
        }
    } else {
        const int pt = t - 128;
        for (int c = 0; c < 8; ++c) {
            const int buf = c & 1;
            char* baseP = smem + buf * BUFSZ;
            if (c >= 2) bar_sync(BAR_EMPTY + buf);
            #pragma unroll
            for (int q = 0; q < 16; ++q) {
                const int idx = pt + q * 128;
                const int n  = idx >> 4;
                const int j4 = (idx & 15) * 4;
                const float4 v = *reinterpret_cast<const float4*>(
                    A + (size_t)(rowBlk + n) * NN + c * 64 + j4);
                uint32_t h0, l0, h1, l1;
                split2(v.x, v.y, h0, l0);
                split2(v.z, v.w, h1, l1);
                *reinterpret_cast<uint2*>(baseP + n * TSTR + j4 * 2)         = make_uint2(h0, h1);
                *reinterpret_cast<uint2*>(baseP + OB_AL + n * TSTR + j4 * 2) = make_uint2(l0, l1);
            }
            #pragma unroll
            for (int q = 0; q < 8; ++q) {
                const int idx = pt + q * 128;
                const int k  = idx >> 4;
                const int i4 = (idx & 15) * 4;
                const float4 v = *reinterpret_cast<const float4*>(
                    Bm + (size_t)(c * 64 + k) * DIN_ + i4);
                uint32_t h0, l0, h1, l1;
                split2(v.x, v.y, h0, l0);
                split2(v.z, v.w, h1, l1);
                *reinterpret_cast<uint2*>(baseP + OB_BH + k * TSTR + i4 * 2) = make_uint2(h0, h1);
                *reinterpret_cast<uint2*>(baseP + OB_BL + k * TSTR + i4 * 2) = make_uint2(l0, l1);
            }
            bar_arrive(BAR_FULL + buf);
        }
    }
}

// ===========================================================================
// Fused contraction: SINGLE-product fp16 (A fp16, W fp16), pair-processed.
// fin[n,o] = sum_d STE[n,d] * (h @ W[d])[n,o] + (STE @ bias)[n,o]
// A resident in smem (fp16, cols 0..191 h, 192..223 STE), fragments cached
// per kc. B: 8 rotating slots (pairs, lookahead 3) + slot 8 = bias tile.
// 512 threads, 4x4 warp grid (32x16 per warp).
// smem: A 59392 | sT 16384 | B 9x9216 = 158720 B
// ===========================================================================
#define A_STR    464u
#define OFF_ST2  59392
#define OFF_B2   75776
#define BSLOT    9216
#define F_SMEM   158720

__global__ __launch_bounds__(512, 1) void fused_mma(
    const float* __restrict__ STE,
    float* __restrict__ out)
{
    extern __shared__ char smem[];
    const int b     = blockIdx.y;
    const int nBase = blockIdx.x * 128;
    const int t    = threadIdx.x;
    const int wid  = t >> 5;
    const int lane = t & 31;
    const int wy   = wid & 3;      // row group (4 x 32 rows)
    const int wx   = wid >> 2;     // col group (4 x 16 cols)
    const uint32_t sb = smem_u32(smem);
    float* sT = reinterpret_cast<float*>(smem + OFF_ST2);

    // ---- Build static A (fp16): h cols 0..191, STE cols 192..223 ----
    {
        const float* hsrc = g_h + (size_t)b * (CHEB * NN * DIN_);
        #pragma unroll
        for (int it = 0; it < 12; ++it) {
            const int idx = t + it * 512;          // 0..6143 float4s
            const int i4 = (idx & 15) * 4;
            const int n  = (idx >> 4) & 127;
            const int k  = idx >> 11;
            const float4 v = *reinterpret_cast<const float4*>(
                hsrc + ((size_t)k * NN + nBase + n) * DIN_ + i4);
            const uint32_t boff = (uint32_t)n * A_STR + (uint32_t)(k * 64 + i4) * 2u;
            *reinterpret_cast<uint2*>(smem + boff) =
                make_uint2(pack2h(v.x, v.y), pack2h(v.z, v.w));
        }
        const float* ssrc = STE + ((size_t)b * NN + nBase) * ET_;
        #pragma unroll
        for (int it = 0; it < 2; ++it) {
            const int idx = t + it * 512;          // 0..1023 float4s
            const int d4 = (idx & 7) * 4;
            const int n  = idx >> 3;
            const float4 v = *reinterpret_cast<const float4*>(ssrc + n * ET_ + d4);
            const uint32_t boff = (uint32_t)n * A_STR + (uint32_t)(192 + d4) * 2u;
            *reinterpret_cast<uint2*>(smem + boff) =
                make_uint2(pack2h(v.x, v.y), pack2h(v.z, v.w));
            sT[(d4 + 0) * 128 + n] = v.x;
            sT[(d4 + 1) * 128 + n] = v.y;
            sT[(d4 + 2) * 128 + n] = v.z;
            sT[(d4 + 3) * 128 + n] = v.w;
        }
    }

    // ---- B tile loader: 576 cp16 per chunk over 512 threads ----
    auto load_chunk = [&](int c, int slot) {
        const uint32_t sbase = sb + OFF_B2 + (uint32_t)slot * BSLOT;
        auto emit = [&](int idx) {
            const int r  = idx / 9;
            const int q9 = idx - r * 9;
            const __half* src = g_Ws + (size_t)c * 4608 + r * 72 + q9 * 8;
            cp16(sbase + (uint32_t)r * TSTR + (uint32_t)q9 * 16u, src);
        };
        emit(t);
        if (t < 64) emit(512 + t);
    };

    // Prologue: bias tile -> slot 8 (1 group), pairs 0..2 -> slots 0..5 (3 groups)
    load_chunk(96, 8); CP_COMMIT();
    #pragma unroll
    for (int p = 0; p < 3; ++p) {
        load_chunk(2 * p,     (2 * p)     & 7);
        load_chunk(2 * p + 1, (2 * p + 1) & 7);
        CP_COMMIT();
    }

    float fin[2][2][4];
    #pragma unroll
    for (int mt = 0; mt < 2; ++mt)
        #pragma unroll
        for (int ng = 0; ng < 2; ++ng)
            #pragma unroll
            for (int e = 0; e < 4; ++e) fin[mt][ng][e] = 0.f;

    const uint32_t rowSel  = (uint32_t)(wy * 32 + (lane & 15));
    const uint32_t kSel    = (uint32_t)((lane >> 4) << 3);
    const uint32_t bRow    = (uint32_t)((lane & 7) + (((lane >> 3) & 1) << 3));
    const uint32_t bColOff = (uint32_t)((wx * 16 + ((lane >> 4) << 3)) * 2);
    const int rl0 = wy * 32 + (lane >> 2);

    uint32_t ahc[4][2][4];   // cached A fragments (fp16): [kstep][mt][4]

    // process one chunk c (0..95) from slot
    auto do_chunk = [&](int c, int slot) {
        const int kc = c >> 5;
        const int d  = c & 31;
        if (d == 0) {   // refresh cached A fragments for this kc
            #pragma unroll
            for (int ks = 0; ks < 4; ++ks)
                #pragma unroll
                for (int mt = 0; mt < 2; ++mt) {
                    const uint32_t off = (rowSel + (uint32_t)(mt * 16)) * A_STR
                                       + (uint32_t)(kc * 64 + ks * 16 + kSel) * 2u;
                    ldsm_x4(ahc[ks][mt][0], ahc[ks][mt][1],
                            ahc[ks][mt][2], ahc[ks][mt][3], sb + off);
                }
        }
        const uint32_t bbase = sb + OFF_B2 + (uint32_t)slot * BSLOT;
        float part[2][2][4];
        #pragma unroll
        for (int mt = 0; mt < 2; ++mt)
            #pragma unroll
            for (int ng = 0; ng < 2; ++ng)
                #pragma unroll
                for (int e = 0; e < 4; ++e) part[mt][ng][e] = 0.f;
        #pragma unroll
        for (int ks = 0; ks < 4; ++ks) {
            const uint32_t boff = ((uint32_t)(ks * 16) + bRow) * TSTR + bColOff;
            uint32_t b0, b1, b2, b3;
            ldsm_x4t(b0, b1, b2, b3, bbase + boff);
            #pragma unroll
            for (int mt = 0; mt < 2; ++mt) {
                mma_fp16(part[mt][0], ahc[ks][mt], b0, b1);
                mma_fp16(part[mt][1], ahc[ks][mt], b2, b3);
            }
        }
        #pragma unroll
        for (int mt = 0; mt < 2; ++mt) {
            const float s0 = sT[d * 128 + rl0 + mt * 16];
            const float s1 = sT[d * 128 + rl0 + mt * 16 + 8];
            #pragma unroll
            for (int ng = 0; ng < 2; ++ng) {
                fin[mt][ng][0] += s0 * part[mt][ng][0];
                fin[mt][ng][1] += s0 * part[mt][ng][1];
                fin[mt][ng][2] += s1 * part[mt][ng][2];
                fin[mt][ng][3] += s1 * part[mt][ng][3];
            }
        }
    };

    for (int p = 0; p < 48; ++p) {
        CP_WAIT2();              // pair p (and bias) landed; pairs p+1, p+2 may fly
        __syncthreads();
        if (p + 3 < 48) {        // refill pair (p+3) into pair (p-1)'s slots
            load_chunk(2 * p + 6, (2 * p + 6) & 7);
            load_chunk(2 * p + 7, (2 * p + 7) & 7);
        }
        CP_COMMIT();             // unconditional: keep group count aligned
        do_chunk(2 * p,     (2 * p)     & 7);
        do_chunk(2 * p + 1, (2 * p + 1) & 7);
    }

    // ---- Bias chunk c=96 (K=32, A cols 192..223), slot 8, unscaled ----
    {
        const uint32_t bbase = sb + OFF_B2 + 8u * BSLOT;
        #pragma unroll
        for (int ks = 0; ks < 2; ++ks) {
            uint32_t ah[2][4];
            #pragma unroll
            for (int mt = 0; mt < 2; ++mt) {
                const uint32_t off = (rowSel + (uint32_t)(mt * 16)) * A_STR
                                   + (uint32_t)(192 + ks * 16 + kSel) * 2u;
                ldsm_x4(ah[mt][0], ah[mt][1], ah[mt][2], ah[mt][3], sb + off);
            }
            const uint32_t boff = ((uint32_t)(ks * 16) + bRow) * TSTR + bColOff;
            uint32_t b0, b1, b2, b3;
            ldsm_x4t(b0, b1, b2, b3, bbase + boff);
            #pragma unroll
            for (int mt = 0; mt < 2; ++mt) {
                mma_fp16(fin[mt][0], ah[mt], b0, b1);
                mma_fp16(fin[mt][1], ah[mt], b2, b3);
            }
        }
    }

    // Epilogue
    const int r0   = nBase + rl0;
    const int col0 = wx * 16 + 2 * (lane & 3);
    float* ob = out + (size_t)b * NN * DOUT_;
    #pragma unroll
    for (int mt = 0; mt < 2; ++mt) {
        #pragma unroll
        for (int ng = 0; ng < 2; ++ng) {
            const int row = r0 + mt * 16;
            const int cc  = col0 + ng * 8;
            *reinterpret_cast<float2*>(ob + (size_t)row * DOUT_ + cc) =
                make_float2(fin[mt][ng][0], fin[mt][ng][1]);
            *reinterpret_cast<float2*>(ob + (size_t)(row + 8) * DOUT_ + cc) =
                make_float2(fin[mt][ng][2], fin[mt][ng][3]);
        }
    }
}

// ===========================================================================
// Launch. Inputs: x, STE, R, SC, weights_pool, bias_pool.
// ===========================================================================
extern "C" void kernel_launch(void* const* d_in, const int* in_sizes, int n_in,
                              void* d_out, int out_size)
{
    (void)in_sizes; (void)n_in; (void)out_size;
    const float* x     = (const float*)d_in[0];
    const float* STE   = (const float*)d_in[1];
    const float* R     = (const float*)d_in[2];
    const float* SC    = (const float*)d_in[3];
    const float* Wp    = (const float*)d_in[4];
    const float* biasp = (const float*)d_in[5];
    float* out = (float*)d_out;

    cudaFuncSetAttribute(prop_mma<0>, cudaFuncAttributeMaxDynamicSharedMemorySize, P_SMEM);
    cudaFuncSetAttribute(prop_mma<1>, cudaFuncAttributeMaxDynamicSharedMemorySize, P_SMEM);
    cudaFuncSetAttribute(fused_mma,   cudaFuncAttributeMaxDynamicSharedMemorySize, F_SMEM);

    prep_w<<<97, 256>>>(Wp, biasp);
    prop_mma<0><<<dim3(NN / 128, NB, 2), 256, P_SMEM>>>(R, SC, x);
    prop_mma<1><<<dim3(NN / 128, NB, 1), 256, P_SMEM>>>(R, SC, x);
    fused_mma<<<dim3(NN / 128, NB), 512, F_SMEM>>>(STE, out);
}

// round 12
// speedup vs baseline: 5.0613x; 1.0904x over previous
#include <cuda_runtime.h>
#include <cuda_bf16.h>
#include <cuda_fp16.h>
#include <cstdint>
#include <cstddef>

// Problem constants
#define NB    32
#define NN    512
#define DIN_  64
#define DOUT_ 64
#define ET_   32
#define CHEB  3
#define KI_   (CHEB * DIN_)   // 192

// Scratch: h[b][k][n][i]  fp32 (12.6 MB)
__device__ float g_h[(size_t)NB * CHEB * NN * DIN_];
// Pre-converted W (+bias as chunk 96), KC-MAJOR: c = kc*32 + d, bias at 96.
// fp16: [97 chunks][64 rows][72 cols] (144B rows)
__device__ __align__(16) __half g_Ws[97 * 64 * 72];

#define TSTR 144u   // tile row stride bytes (odd multiple of 16B)

// ===========================================================================
// PTX helpers
// ===========================================================================
__device__ __forceinline__ uint32_t smem_u32(const void* p) {
    uint32_t a;
    asm("{ .reg .u64 t; cvta.to.shared.u64 t, %1; cvt.u32.u64 %0, t; }"
        : "=r"(a) : "l"(p));
    return a;
}
__device__ __forceinline__ void ldsm_x4(uint32_t& r0, uint32_t& r1,
                                        uint32_t& r2, uint32_t& r3, uint32_t addr) {
    asm volatile("ldmatrix.sync.aligned.m8n8.x4.shared.b16 {%0,%1,%2,%3}, [%4];"
                 : "=r"(r0), "=r"(r1), "=r"(r2), "=r"(r3) : "r"(addr));
}
__device__ __forceinline__ void ldsm_x4t(uint32_t& r0, uint32_t& r1,
                                         uint32_t& r2, uint32_t& r3, uint32_t addr) {
    asm volatile("ldmatrix.sync.aligned.m8n8.x4.trans.shared.b16 {%0,%1,%2,%3}, [%4];"
                 : "=r"(r0), "=r"(r1), "=r"(r2), "=r"(r3) : "r"(addr));
}
__device__ __forceinline__ void mma_fp16(float* c, const uint32_t* a,
                                         uint32_t b0, uint32_t b1) {
    asm volatile(
        "mma.sync.aligned.m16n8k16.row.col.f32.f16.f16.f32 "
        "{%0,%1,%2,%3}, {%4,%5,%6,%7}, {%8,%9}, {%0,%1,%2,%3};"
        : "+f"(c[0]), "+f"(c[1]), "+f"(c[2]), "+f"(c[3])
        : "r"(a[0]), "r"(a[1]), "r"(a[2]), "r"(a[3]), "r"(b0), "r"(b1));
}
__device__ __forceinline__ void cp16(uint32_t dst, const void* src) {
    asm volatile("cp.async.ca.shared.global [%0], [%1], 16;" :: "r"(dst), "l"(src));
}
#define CP_COMMIT() asm volatile("cp.async.commit_group;" ::: "memory")
#define CP_WAIT2()  asm volatile("cp.async.wait_group 2;" ::: "memory")
__device__ __forceinline__ void bar_sync(int id) {
    asm volatile("bar.sync %0, 256;" :: "r"(id) : "memory");
}
__device__ __forceinline__ void bar_arrive(int id) {
    asm volatile("bar.arrive %0, 256;" :: "r"(id) : "memory");
}
#define BAR_FULL  1
#define BAR_EMPTY 3

// fp16 pack
__device__ __forceinline__ uint32_t pack2h(float p0, float p1) {
    uint32_t r;
    asm("cvt.rn.f16x2.f32 %0, %1, %2;" : "=r"(r) : "f"(p1), "f"(p0));
    return r;
}

// ===========================================================================
// Precompute: convert W (+bias chunk 96) to padded fp16 tiles, kc-major.
// ===========================================================================
__global__ __launch_bounds__(256) void prep_w(const float* __restrict__ Wp,
                                              const float* __restrict__ biasp) {
    const int c = blockIdx.x;
    const int t = threadIdx.x;
    __half* hi = g_Ws + (size_t)c * 64 * 72;
    #pragma unroll
    for (int it = 0; it < 4; ++it) {
        const int idx = t + it * 256;
        const int k  = idx >> 4;
        const int o4 = (idx & 15) * 4;
        float4 v = make_float4(0.f, 0.f, 0.f, 0.f);
        if (c < 96) {
            const int kc = c >> 5, d = c & 31;
            v = *reinterpret_cast<const float4*>(Wp + ((size_t)(d * KI_ + kc * 64 + k)) * DOUT_ + o4);
        } else if (k < 32) {
            v = *reinterpret_cast<const float4*>(biasp + (size_t)k * DOUT_ + o4);
        }
        *reinterpret_cast<uint2*>(hi + k * 72 + o4) =
            make_uint2(pack2h(v.x, v.y), pack2h(v.z, v.w));
    }
    if (t < 64)
        *reinterpret_cast<uint4*>(hi + t * 72 + 64) = make_uint4(0, 0, 0, 0);
}

// ===========================================================================
// Prop kernels: single-product fp16, warp-specialized, 2 CTAs/SM.
// C[512x64] = A[512x512] @ Bm[512x64].
// MODE 0: z selects SC->h0 / R->h1, Bm=x.  MODE 1: A=R, Bm=h1, C=2*acc-h0 -> h2
// smem: 2 buffers x {A 18432 | B 9216} = 55296 B
// ===========================================================================
#define BUFSZ   27648
#define OB_B    18432
#define P_SMEM  (2 * BUFSZ)

__device__ __forceinline__ void mma_chunk_h(float acc[2][8][4],
                                            uint32_t aBase, uint32_t bBase,
                                            int warp, int lane) {
    const uint32_t rowSel = (uint32_t)(warp * 32 + (lane & 15));
    const uint32_t kSel   = (uint32_t)((lane >> 4) << 3);
    const uint32_t bRow   = (uint32_t)((lane & 7) + (((lane >> 3) & 1) << 3));
    const uint32_t bCol   = (uint32_t)((lane >> 4) << 3);
    #pragma unroll
    for (int ks = 0; ks < 4; ++ks) {
        const uint32_t kb = (uint32_t)(ks * 16);
        uint32_t ah[2][4];
        #pragma unroll
        for (int mt = 0; mt < 2; ++mt) {
            const uint32_t off = (rowSel + (uint32_t)(mt * 16)) * TSTR + (kb + kSel) * 2u;
            ldsm_x4(ah[mt][0], ah[mt][1], ah[mt][2], ah[mt][3], aBase + off);
        }
        #pragma unroll
        for (int g = 0; g < 4; ++g) {     // 16-col groups
            const uint32_t boff = (kb + bRow) * TSTR + ((uint32_t)(g * 16) + bCol) * 2u;
            uint32_t b0, b1, b2, b3;
            ldsm_x4t(b0, b1, b2, b3, bBase + boff);
            #pragma unroll
            for (int mt = 0; mt < 2; ++mt) {
                mma_fp16(acc[mt][2 * g],     ah[mt], b0, b1);
                mma_fp16(acc[mt][2 * g + 1], ah[mt], b2, b3);
            }
        }
    }
}

template<int MODE>
__global__ __launch_bounds__(256, 2) void prop_mma(
    const float* __restrict__ R,
    const float* __restrict__ SC,
    const float* __restrict__ X)
{
    extern __shared__ char smem[];
    const int b = blockIdx.y;
    const int rowBlk = blockIdx.x * 128;

    float* hb = g_h + (size_t)b * (CHEB * NN * DIN_);
    const float* A;
    const float* Bm;
    const float* Sub = nullptr;
    float* C;
    if (MODE == 0) {
        const int which = blockIdx.z;
        A  = (which == 0 ? SC : R) + (size_t)b * NN * NN;
        Bm = X + (size_t)b * NN * DIN_;
        C  = hb + (size_t)which * NN * DIN_;
    } else {
        A   = R  + (size_t)b * NN * NN;
        Bm  = hb + (size_t)1 * NN * DIN_;
        Sub = hb + (size_t)0 * NN * DIN_;
        C   = hb + (size_t)2 * NN * DIN_;
    }

    const int t    = threadIdx.x;
    const int wid  = t >> 5;
    const int lane = t & 31;
    const uint32_t sb = smem_u32(smem);

    if (wid < 4) {
        // ---------------- consumer ----------------
        float acc[2][8][4];
        #pragma unroll
        for (int mt = 0; mt < 2; ++mt)
            #pragma unroll
            for (int nt = 0; nt < 8; ++nt)
                #pragma unroll
                for (int e = 0; e < 4; ++e) acc[mt][nt][e] = 0.f;

        for (int c = 0; c < 8; ++c) {
            const int buf = c & 1;
            const uint32_t base = sb + buf * BUFSZ;
            bar_sync(BAR_FULL + buf);
            mma_chunk_h(acc, base, base + OB_B, wid, lane);
            bar_arrive(BAR_EMPTY + buf);
        }
        const int r0   = rowBlk + wid * 32 + (lane >> 2);
        const int col0 = 2 * (lane & 3);
        #pragma unroll
        for (int mt = 0; mt < 2; ++mt) {
            #pragma unroll
            for (int nt = 0; nt < 8; ++nt) {
                const int row = r0 + mt * 16;
                const int cc  = col0 + nt * 8;
                float2 v0, v1;
                if (MODE == 1) {
                    const float2 s0 = *reinterpret_cast<const float2*>(Sub + (size_t)row * DIN_ + cc);
                    const float2 s1 = *reinterpret_cast<const float2*>(Sub + (size_t)(row + 8) * DIN_ + cc);
                    v0 = make_float2(2.f * acc[mt][nt][0] - s0.x, 2.f * acc[mt][nt][1] - s0.y);
                    v1 = make_float2(2.f * acc[mt][nt][2] - s1.x, 2.f * acc[mt][nt][3] - s1.y);
                } else {
                    v0 = make_float2(acc[mt][nt][0], acc[mt][nt][1]);
                    v1 = make_float2(acc[mt][nt][2], acc[mt][nt][3]);
                }
                *reinterpret_cast<float2*>(C + (size_t)row * DIN_ + cc)       = v0;
                *reinterpret_cast<float2*>(C + (size_t)(row + 8) * DIN_ + cc) = v1;
            }
        }
    } else {
        // ---------------- producer (fp16 pack, no residual) ----------------
        const int pt = t - 128;
        for (int c = 0; c < 8; ++c) {
            const int buf = c & 1;
            char* baseP = smem + buf * BUFSZ;
            if (c >= 2) bar_sync(BAR_EMPTY + buf);
            // A chunk [128 n][64 k]: 2048 float4s, 16/thread, coalesced
            #pragma unroll
            for (int q = 0; q < 16; ++q) {
                const int idx = pt + q * 128;
                const int n  = idx >> 4;
                const int j4 = (idx & 15) * 4;
                const float4 v = *reinterpret_cast<const float4*>(
                    A + (size_t)(rowBlk + n) * NN + c * 64 + j4);
                *reinterpret_cast<uint2*>(baseP + n * TSTR + j4 * 2) =
                    make_uint2(pack2h(v.x, v.y), pack2h(v.z, v.w));
            }
            // B chunk [64 k][64 i]: 1024 float4s, 8/thread
            #pragma unroll
            for (int q = 0; q < 8; ++q) {
                const int idx = pt + q * 128;
                const int k  = idx >> 4;
                const int i4 = (idx & 15) * 4;
                const float4 v = *reinterpret_cast<const float4*>(
                    Bm + (size_t)(c * 64 + k) * DIN_ + i4);
                *reinterpret_cast<uint2*>(baseP + OB_B + k * TSTR + i4 * 2) =
                    make_uint2(pack2h(v.x, v.y), pack2h(v.z, v.w));
            }
            bar_arrive(BAR_FULL + buf);
        }
    }
}

// ===========================================================================
// Fused contraction (unchanged from round 11): single-product fp16,
// pair-processed, A resident, per-kc register-cached A fragments.
// smem: A 59392 | sT 16384 | B 9x9216 = 158720 B
// ===========================================================================
#define A_STR    464u
#define OFF_ST2  59392
#define OFF_B2   75776
#define BSLOT    9216
#define F_SMEM   158720

__global__ __launch_bounds__(512, 1) void fused_mma(
    const float* __restrict__ STE,
    float* __restrict__ out)
{
    extern __shared__ char smem[];
    const int b     = blockIdx.y;
    const int nBase = blockIdx.x * 128;
    const int t    = threadIdx.x;
    const int wid  = t >> 5;
    const int lane = t & 31;
    const int wy   = wid & 3;
    const int wx   = wid >> 2;
    const uint32_t sb = smem_u32(smem);
    float* sT = reinterpret_cast<float*>(smem + OFF_ST2);

    // ---- Build static A (fp16): h cols 0..191, STE cols 192..223 ----
    {
        const float* hsrc = g_h + (size_t)b * (CHEB * NN * DIN_);
        #pragma unroll
        for (int it = 0; it < 12; ++it) {
            const int idx = t + it * 512;
            const int i4 = (idx & 15) * 4;
            const int n  = (idx >> 4) & 127;
            const int k  = idx >> 11;
            const float4 v = *reinterpret_cast<const float4*>(
                hsrc + ((size_t)k * NN + nBase + n) * DIN_ + i4);
            const uint32_t boff = (uint32_t)n * A_STR + (uint32_t)(k * 64 + i4) * 2u;
            *reinterpret_cast<uint2*>(smem + boff) =
                make_uint2(pack2h(v.x, v.y), pack2h(v.z, v.w));
        }
        const float* ssrc = STE + ((size_t)b * NN + nBase) * ET_;
        #pragma unroll
        for (int it = 0; it < 2; ++it) {
            const int idx = t + it * 512;
            const int d4 = (idx & 7) * 4;
            const int n  = idx >> 3;
            const float4 v = *reinterpret_cast<const float4*>(ssrc + n * ET_ + d4);
            const uint32_t boff = (uint32_t)n * A_STR + (uint32_t)(192 + d4) * 2u;
            *reinterpret_cast<uint2*>(smem + boff) =
                make_uint2(pack2h(v.x, v.y), pack2h(v.z, v.w));
            sT[(d4 + 0) * 128 + n] = v.x;
            sT[(d4 + 1) * 128 + n] = v.y;
            sT[(d4 + 2) * 128 + n] = v.z;
            sT[(d4 + 3) * 128 + n] = v.w;
        }
    }

    auto load_chunk = [&](int c, int slot) {
        const uint32_t sbase = sb + OFF_B2 + (uint32_t)slot * BSLOT;
        auto emit = [&](int idx) {
            const int r  = idx / 9;
            const int q9 = idx - r * 9;
            const __half* src = g_Ws + (size_t)c * 4608 + r * 72 + q9 * 8;
            cp16(sbase + (uint32_t)r * TSTR + (uint32_t)q9 * 16u, src);
        };
        emit(t);
        if (t < 64) emit(512 + t);
    };

    load_chunk(96, 8); CP_COMMIT();
    #pragma unroll
    for (int p = 0; p < 3; ++p) {
        load_chunk(2 * p,     (2 * p)     & 7);
        load_chunk(2 * p + 1, (2 * p + 1) & 7);
        CP_COMMIT();
    }

    float fin[2][2][4];
    #pragma unroll
    for (int mt = 0; mt < 2; ++mt)
        #pragma unroll
        for (int ng = 0; ng < 2; ++ng)
            #pragma unroll
            for (int e = 0; e < 4; ++e) fin[mt][ng][e] = 0.f;

    const uint32_t rowSel  = (uint32_t)(wy * 32 + (lane & 15));
    const uint32_t kSel    = (uint32_t)((lane >> 4) << 3);
    const uint32_t bRow    = (uint32_t)((lane & 7) + (((lane >> 3) & 1) << 3));
    const uint32_t bColOff = (uint32_t)((wx * 16 + ((lane >> 4) << 3)) * 2);
    const int rl0 = wy * 32 + (lane >> 2);

    uint32_t ahc[4][2][4];

    auto do_chunk = [&](int c, int slot) {
        const int kc = c >> 5;
        const int d  = c & 31;
        if (d == 0) {
            #pragma unroll
            for (int ks = 0; ks < 4; ++ks)
                #pragma unroll
                for (int mt = 0; mt < 2; ++mt) {
                    const uint32_t off = (rowSel + (uint32_t)(mt * 16)) * A_STR
                                       + (uint32_t)(kc * 64 + ks * 16 + kSel) * 2u;
                    ldsm_x4(ahc[ks][mt][0], ahc[ks][mt][1],
                            ahc[ks][mt][2], ahc[ks][mt][3], sb + off);
                }
        }
        const uint32_t bbase = sb + OFF_B2 + (uint32_t)slot * BSLOT;
        float part[2][2][4];
        #pragma unroll
        for (int mt = 0; mt < 2; ++mt)
            #pragma unroll
            for (int ng = 0; ng < 2; ++ng)
                #pragma unroll
                for (int e = 0; e < 4; ++e) part[mt][ng][e] = 0.f;
        #pragma unroll
        for (int ks = 0; ks < 4; ++ks) {
            const uint32_t boff = ((uint32_t)(ks * 16) + bRow) * TSTR + bColOff;
            uint32_t b0, b1, b2, b3;
            ldsm_x4t(b0, b1, b2, b3, bbase + boff);
            #pragma unroll
            for (int mt = 0; mt < 2; ++mt) {
                mma_fp16(part[mt][0], ahc[ks][mt], b0, b1);
                mma_fp16(part[mt][1], ahc[ks][mt], b2, b3);
            }
        }
        #pragma unroll
        for (int mt = 0; mt < 2; ++mt) {
            const float s0 = sT[d * 128 + rl0 + mt * 16];
            const float s1 = sT[d * 128 + rl0 + mt * 16 + 8];
            #pragma unroll
            for (int ng = 0; ng < 2; ++ng) {
                fin[mt][ng][0] += s0 * part[mt][ng][0];
                fin[mt][ng][1] += s0 * part[mt][ng][1];
                fin[mt][ng][2] += s1 * part[mt][ng][2];
                fin[mt][ng][3] += s1 * part[mt][ng][3];
            }
        }
    };

    for (int p = 0; p < 48; ++p) {
        CP_WAIT2();
        __syncthreads();
        if (p + 3 < 48) {
            load_chunk(2 * p + 6, (2 * p + 6) & 7);
            load_chunk(2 * p + 7, (2 * p + 7) & 7);
        }
        CP_COMMIT();
        do_chunk(2 * p,     (2 * p)     & 7);
        do_chunk(2 * p + 1, (2 * p + 1) & 7);
    }

    // Bias chunk c=96 (K=32, A cols 192..223), slot 8, unscaled
    {
        const uint32_t bbase = sb + OFF_B2 + 8u * BSLOT;
        #pragma unroll
        for (int ks = 0; ks < 2; ++ks) {
            uint32_t ah[2][4];
            #pragma unroll
            for (int mt = 0; mt < 2; ++mt) {
                const uint32_t off = (rowSel + (uint32_t)(mt * 16)) * A_STR
                                   + (uint32_t)(192 + ks * 16 + kSel) * 2u;
                ldsm_x4(ah[mt][0], ah[mt][1], ah[mt][2], ah[mt][3], sb + off);
            }
            const uint32_t boff = ((uint32_t)(ks * 16) + bRow) * TSTR + bColOff;
            uint32_t b0, b1, b2, b3;
            ldsm_x4t(b0, b1, b2, b3, bbase + boff);
            #pragma unroll
            for (int mt = 0; mt < 2; ++mt) {
                mma_fp16(fin[mt][0], ah[mt], b0, b1);
                mma_fp16(fin[mt][1], ah[mt], b2, b3);
            }
        }
    }

    // Epilogue
    const int r0   = nBase + rl0;
    const int col0 = wx * 16 + 2 * (lane & 3);
    float* ob = out + (size_t)b * NN * DOUT_;
    #pragma unroll
    for (int mt = 0; mt < 2; ++mt) {
        #pragma unroll
        for (int ng = 0; ng < 2; ++ng) {
            const int row = r0 + mt * 16;
            const int cc  = col0 + ng * 8;
            *reinterpret_cast<float2*>(ob + (size_t)row * DOUT_ + cc) =
                make_float2(fin[mt][ng][0], fin[mt][ng][1]);
            *reinterpret_cast<float2*>(ob + (size_t)(row + 8) * DOUT_ + cc) =
                make_float2(fin[mt][ng][2], fin[mt][ng][3]);
        }
    }
}

// ===========================================================================
// Launch. Inputs: x, STE, R, SC, weights_pool, bias_pool.
// ===========================================================================
extern "C" void kernel_launch(void* const* d_in, const int* in_sizes, int n_in,
                              void* d_out, int out_size)
{
    (void)in_sizes; (void)n_in; (void)out_size;
    const float* x     = (const float*)d_in[0];
    const float* STE   = (const float*)d_in[1];
    const float* R     = (const float*)d_in[2];
    const float* SC    = (const float*)d_in[3];
    const float* Wp    = (const float*)d_in[4];
    const float* biasp = (const float*)d_in[5];
    float* out = (float*)d_out;

    cudaFuncSetAttribute(prop_mma<0>, cudaFuncAttributeMaxDynamicSharedMemorySize, P_SMEM);
    cudaFuncSetAttribute(prop_mma<1>, cudaFuncAttributeMaxDynamicSharedMemorySize, P_SMEM);
    cudaFuncSetAttribute(fused_mma,   cudaFuncAttributeMaxDynamicSharedMemorySize, F_SMEM);

    prep_w<<<97, 256>>>(Wp, biasp);
    prop_mma<0><<<dim3(NN / 128, NB, 2), 256, P_SMEM>>>(R, SC, x);
    prop_mma<1><<<dim3(NN / 128, NB, 1), 256, P_SMEM>>>(R, SC, x);
    fused_mma<<<dim3(NN / 128, NB), 512, F_SMEM>>>(STE, out);
}

// round 13
// speedup vs baseline: 5.2274x; 1.0328x over previous
#include <cuda_runtime.h>
#include <cuda_bf16.h>
#include <cuda_fp16.h>
#include <cstdint>
#include <cstddef>

// Problem constants
#define NB    32
#define NN    512
#define DIN_  64
#define DOUT_ 64
#define ET_   32
#define CHEB  3
#define KI_   (CHEB * DIN_)   // 192

// Scratch: h[b][k][n][i]  fp32 (12.6 MB)
__device__ float g_h[(size_t)NB * CHEB * NN * DIN_];
// Pre-converted W (+bias as chunk 96), KC-MAJOR: c = kc*32 + d, bias at 96.
// fp16: [97 chunks][64 rows][72 cols] (144B rows). Written by prop_mma<0>.
__device__ __align__(16) __half g_Ws[97 * 64 * 72];

#define TSTR 144u   // tile row stride bytes (odd multiple of 16B)

// ===========================================================================
// PTX helpers
// ===========================================================================
__device__ __forceinline__ uint32_t smem_u32(const void* p) {
    uint32_t a;
    asm("{ .reg .u64 t; cvta.to.shared.u64 t, %1; cvt.u32.u64 %0, t; }"
        : "=r"(a) : "l"(p));
    return a;
}
__device__ __forceinline__ void ldsm_x4(uint32_t& r0, uint32_t& r1,
                                        uint32_t& r2, uint32_t& r3, uint32_t addr) {
    asm volatile("ldmatrix.sync.aligned.m8n8.x4.shared.b16 {%0,%1,%2,%3}, [%4];"
                 : "=r"(r0), "=r"(r1), "=r"(r2), "=r"(r3) : "r"(addr));
}
__device__ __forceinline__ void ldsm_x4t(uint32_t& r0, uint32_t& r1,
                                         uint32_t& r2, uint32_t& r3, uint32_t addr) {
    asm volatile("ldmatrix.sync.aligned.m8n8.x4.trans.shared.b16 {%0,%1,%2,%3}, [%4];"
                 : "=r"(r0), "=r"(r1), "=r"(r2), "=r"(r3) : "r"(addr));
}
__device__ __forceinline__ void mma_fp16(float* c, const uint32_t* a,
                                         uint32_t b0, uint32_t b1) {
    asm volatile(
        "mma.sync.aligned.m16n8k16.row.col.f32.f16.f16.f32 "
        "{%0,%1,%2,%3}, {%4,%5,%6,%7}, {%8,%9}, {%0,%1,%2,%3};"
        : "+f"(c[0]), "+f"(c[1]), "+f"(c[2]), "+f"(c[3])
        : "r"(a[0]), "r"(a[1]), "r"(a[2]), "r"(a[3]), "r"(b0), "r"(b1));
}
__device__ __forceinline__ void cp16(uint32_t dst, const void* src) {
    asm volatile("cp.async.ca.shared.global [%0], [%1], 16;" :: "r"(dst), "l"(src));
}
#define CP_COMMIT() asm volatile("cp.async.commit_group;" ::: "memory")
#define CP_WAIT2()  asm volatile("cp.async.wait_group 2;" ::: "memory")
__device__ __forceinline__ void bar_sync(int id) {
    asm volatile("bar.sync %0, 256;" :: "r"(id) : "memory");
}
__device__ __forceinline__ void bar_arrive(int id) {
    asm volatile("bar.arrive %0, 256;" :: "r"(id) : "memory");
}
#define BAR_FULL  1
#define BAR_EMPTY 3

// fp16 pack
__device__ __forceinline__ uint32_t pack2h(float p0, float p1) {
    uint32_t r;
    asm("cvt.rn.f16x2.f32 %0, %1, %2;" : "=r"(r) : "f"(p1), "f"(p0));
    return r;
}

// ===========================================================================
// Prop kernels: single-product fp16, warp-specialized, 2 CTAs/SM.
// C[512x64] = A[512x512] @ Bm[512x64].
// MODE 0: z selects SC->h0 / R->h1, Bm=x; 97 of the z=0 CTAs also convert
//         W (+bias) tiles into g_Ws on their (otherwise idle) consumer warps.
// MODE 1: A=R, Bm=h1, C=2*acc-h0 -> h2
// smem: 2 buffers x {A 18432 | B 9216} = 55296 B
// ===========================================================================
#define BUFSZ   27648
#define OB_B    18432
#define P_SMEM  (2 * BUFSZ)

__device__ __forceinline__ void mma_chunk_h(float acc[2][8][4],
                                            uint32_t aBase, uint32_t bBase,
                                            int warp, int lane) {
    const uint32_t rowSel = (uint32_t)(warp * 32 + (lane & 15));
    const uint32_t kSel   = (uint32_t)((lane >> 4) << 3);
    const uint32_t bRow   = (uint32_t)((lane & 7) + (((lane >> 3) & 1) << 3));
    const uint32_t bCol   = (uint32_t)((lane >> 4) << 3);
    #pragma unroll
    for (int ks = 0; ks < 4; ++ks) {
        const uint32_t kb = (uint32_t)(ks * 16);
        uint32_t ah[2][4];
        #pragma unroll
        for (int mt = 0; mt < 2; ++mt) {
            const uint32_t off = (rowSel + (uint32_t)(mt * 16)) * TSTR + (kb + kSel) * 2u;
            ldsm_x4(ah[mt][0], ah[mt][1], ah[mt][2], ah[mt][3], aBase + off);
        }
        #pragma unroll
        for (int g = 0; g < 4; ++g) {     // 16-col groups
            const uint32_t boff = (kb + bRow) * TSTR + ((uint32_t)(g * 16) + bCol) * 2u;
            uint32_t b0, b1, b2, b3;
            ldsm_x4t(b0, b1, b2, b3, bBase + boff);
            #pragma unroll
            for (int mt = 0; mt < 2; ++mt) {
                mma_fp16(acc[mt][2 * g],     ah[mt], b0, b1);
                mma_fp16(acc[mt][2 * g + 1], ah[mt], b2, b3);
            }
        }
    }
}

template<int MODE>
__global__ __launch_bounds__(256, 2) void prop_mma(
    const float* __restrict__ R,
    const float* __restrict__ SC,
    const float* __restrict__ X,
    const float* __restrict__ Wp,
    const float* __restrict__ biasp)
{
    extern __shared__ char smem[];
    const int b = blockIdx.y;
    const int rowBlk = blockIdx.x * 128;

    float* hb = g_h + (size_t)b * (CHEB * NN * DIN_);
    const float* A;
    const float* Bm;
    const float* Sub = nullptr;
    float* C;
    if (MODE == 0) {
        const int which = blockIdx.z;
        A  = (which == 0 ? SC : R) + (size_t)b * NN * NN;
        Bm = X + (size_t)b * NN * DIN_;
        C  = hb + (size_t)which * NN * DIN_;
    } else {
        A   = R  + (size_t)b * NN * NN;
        Bm  = hb + (size_t)1 * NN * DIN_;
        Sub = hb + (size_t)0 * NN * DIN_;
        C   = hb + (size_t)2 * NN * DIN_;
    }

    const int t    = threadIdx.x;
    const int wid  = t >> 5;
    const int lane = t & 31;
    const uint32_t sb = smem_u32(smem);

    if (wid < 4) {
        // ---- Embedded W prep (MODE 0, z=0, first 97 CTAs; consumer warps
        //      are otherwise idle while producers fill buffer 0) ----
        if (MODE == 0 && blockIdx.z == 0) {
            const int id = blockIdx.x + (NN / 128) * blockIdx.y;   // 0..127
            if (id < 97) {
                __half* hi = g_Ws + (size_t)id * 64 * 72;
                #pragma unroll
                for (int it = 0; it < 8; ++it) {
                    const int idx = t + it * 128;      // 0..1023
                    const int k  = idx >> 4;
                    const int o4 = (idx & 15) * 4;
                    float4 v = make_float4(0.f, 0.f, 0.f, 0.f);
                    if (id < 96) {
                        const int kc = id >> 5, d = id & 31;
                        v = *reinterpret_cast<const float4*>(
                            Wp + ((size_t)(d * KI_ + kc * 64 + k)) * DOUT_ + o4);
                    } else if (k < 32) {
                        v = *reinterpret_cast<const float4*>(biasp + (size_t)k * DOUT_ + o4);
                    }
                    *reinterpret_cast<uint2*>(hi + k * 72 + o4) =
                        make_uint2(pack2h(v.x, v.y), pack2h(v.z, v.w));
                }
                if (t < 64)
                    *reinterpret_cast<uint4*>(hi + t * 72 + 64) = make_uint4(0, 0, 0, 0);
            }
        }

        // ---------------- consumer ----------------
        float acc[2][8][4];
        #pragma unroll
        for (int mt = 0; mt < 2; ++mt)
            #pragma unroll
            for (int nt = 0; nt < 8; ++nt)
                #pragma unroll
                for (int e = 0; e < 4; ++e) acc[mt][nt][e] = 0.f;

        for (int c = 0; c < 8; ++c) {
            const int buf = c & 1;
            const uint32_t base = sb + buf * BUFSZ;
            bar_sync(BAR_FULL + buf);
            mma_chunk_h(acc, base, base + OB_B, wid, lane);
            bar_arrive(BAR_EMPTY + buf);
        }
        const int r0   = rowBlk + wid * 32 + (lane >> 2);
        const int col0 = 2 * (lane & 3);
        #pragma unroll
        for (int mt = 0; mt < 2; ++mt) {
            #pragma unroll
            for (int nt = 0; nt < 8; ++nt) {
                const int row = r0 + mt * 16;
                const int cc  = col0 + nt * 8;
                float2 v0, v1;
                if (MODE == 1) {
                    const float2 s0 = *reinterpret_cast<const float2*>(Sub + (size_t)row * DIN_ + cc);
                    const float2 s1 = *reinterpret_cast<const float2*>(Sub + (size_t)(row + 8) * DIN_ + cc);
                    v0 = make_float2(2.f * acc[mt][nt][0] - s0.x, 2.f * acc[mt][nt][1] - s0.y);
                    v1 = make_float2(2.f * acc[mt][nt][2] - s1.x, 2.f * acc[mt][nt][3] - s1.y);
                } else {
                    v0 = make_float2(acc[mt][nt][0], acc[mt][nt][1]);
                    v1 = make_float2(acc[mt][nt][2], acc[mt][nt][3]);
                }
                *reinterpret_cast<float2*>(C + (size_t)row * DIN_ + cc)       = v0;
                *reinterpret_cast<float2*>(C + (size_t)(row + 8) * DIN_ + cc) = v1;
            }
        }
    } else {
        // ---------------- producer (fp16 pack) ----------------
        const int pt = t - 128;
        for (int c = 0; c < 8; ++c) {
            const int buf = c & 1;
            char* baseP = smem + buf * BUFSZ;
            if (c >= 2) bar_sync(BAR_EMPTY + buf);
            #pragma unroll
            for (int q = 0; q < 16; ++q) {
                const int idx = pt + q * 128;
                const int n  = idx >> 4;
                const int j4 = (idx & 15) * 4;
                const float4 v = *reinterpret_cast<const float4*>(
                    A + (size_t)(rowBlk + n) * NN + c * 64 + j4);
                *reinterpret_cast<uint2*>(baseP + n * TSTR + j4 * 2) =
                    make_uint2(pack2h(v.x, v.y), pack2h(v.z, v.w));
            }
            #pragma unroll
            for (int q = 0; q < 8; ++q) {
                const int idx = pt + q * 128;
                const int k  = idx >> 4;
                const int i4 = (idx & 15) * 4;
                const float4 v = *reinterpret_cast<const float4*>(
                    Bm + (size_t)(c * 64 + k) * DIN_ + i4);
                *reinterpret_cast<uint2*>(baseP + OB_B + k * TSTR + i4 * 2) =
                    make_uint2(pack2h(v.x, v.y), pack2h(v.z, v.w));
            }
            bar_arrive(BAR_FULL + buf);
        }
    }
}

// ===========================================================================
// Fused contraction: single-product fp16, TRIPLE-chunk processing.
// fin[n,o] = sum_d STE[n,d] * (h @ W[d])[n,o] + (STE @ bias)[n,o]
// A resident in smem (fp16, cols 0..191 h, 192..223 STE), fragments cached
// per kc. B: 12 rotating slots (trips of 3 chunks, slot = c % 12, lookahead
// 3 trips) + slot 12 = bias tile. 512 threads, 4x4 warp grid.
// smem: A 59392 | sT 16384 | B 13x9216 = 195584 B
// ===========================================================================
#define A_STR    464u
#define OFF_ST2  59392
#define OFF_B2   75776
#define BSLOT    9216
#define F_SMEM   195584

__global__ __launch_bounds__(512, 1) void fused_mma(
    const float* __restrict__ STE,
    float* __restrict__ out)
{
    extern __shared__ char smem[];
    const int b     = blockIdx.y;
    const int nBase = blockIdx.x * 128;
    const int t    = threadIdx.x;
    const int wid  = t >> 5;
    const int lane = t & 31;
    const int wy   = wid & 3;
    const int wx   = wid >> 2;
    const uint32_t sb = smem_u32(smem);
    float* sT = reinterpret_cast<float*>(smem + OFF_ST2);

    // ---- Build static A (fp16): h cols 0..191, STE cols 192..223 ----
    {
        const float* hsrc = g_h + (size_t)b * (CHEB * NN * DIN_);
        #pragma unroll
        for (int it = 0; it < 12; ++it) {
            const int idx = t + it * 512;
            const int i4 = (idx & 15) * 4;
            const int n  = (idx >> 4) & 127;
            const int k  = idx >> 11;
            const float4 v = *reinterpret_cast<const float4*>(
                hsrc + ((size_t)k * NN + nBase + n) * DIN_ + i4);
            const uint32_t boff = (uint32_t)n * A_STR + (uint32_t)(k * 64 + i4) * 2u;
            *reinterpret_cast<uint2*>(smem + boff) =
                make_uint2(pack2h(v.x, v.y), pack2h(v.z, v.w));
        }
        const float* ssrc = STE + ((size_t)b * NN + nBase) * ET_;
        #pragma unroll
        for (int it = 0; it < 2; ++it) {
            const int idx = t + it * 512;
            const int d4 = (idx & 7) * 4;
            const int n  = idx >> 3;
            const float4 v = *reinterpret_cast<const float4*>(ssrc + n * ET_ + d4);
            const uint32_t boff = (uint32_t)n * A_STR + (uint32_t)(192 + d4) * 2u;
            *reinterpret_cast<uint2*>(smem + boff) =
                make_uint2(pack2h(v.x, v.y), pack2h(v.z, v.w));
            sT[(d4 + 0) * 128 + n] = v.x;
            sT[(d4 + 1) * 128 + n] = v.y;
            sT[(d4 + 2) * 128 + n] = v.z;
            sT[(d4 + 3) * 128 + n] = v.w;
        }
    }

    auto load_chunk = [&](int c, int slot) {
        const uint32_t sbase = sb + OFF_B2 + (uint32_t)slot * BSLOT;
        auto emit = [&](int idx) {
            const int r  = idx / 9;
            const int q9 = idx - r * 9;
            const __half* src = g_Ws + (size_t)c * 4608 + r * 72 + q9 * 8;
            cp16(sbase + (uint32_t)r * TSTR + (uint32_t)q9 * 16u, src);
        };
        emit(t);
        if (t < 64) emit(512 + t);
    };

    // Prologue: bias -> slot 12 (group 0); trips 0..2 -> slots 0..8 (groups 1-3)
    load_chunk(96, 12); CP_COMMIT();
    #pragma unroll
    for (int p = 0; p < 3; ++p) {
        load_chunk(3 * p,     (3 * p)     % 12);
        load_chunk(3 * p + 1, (3 * p + 1) % 12);
        load_chunk(3 * p + 2, (3 * p + 2) % 12);
        CP_COMMIT();
    }

    float fin[2][2][4];
    #pragma unroll
    for (int mt = 0; mt < 2; ++mt)
        #pragma unroll
        for (int ng = 0; ng < 2; ++ng)
            #pragma unroll
            for (int e = 0; e < 4; ++e) fin[mt][ng][e] = 0.f;

    const uint32_t rowSel  = (uint32_t)(wy * 32 + (lane & 15));
    const uint32_t kSel    = (uint32_t)((lane >> 4) << 3);
    const uint32_t bRow    = (uint32_t)((lane & 7) + (((lane >> 3) & 1) << 3));
    const uint32_t bColOff = (uint32_t)((wx * 16 + ((lane >> 4) << 3)) * 2);
    const int rl0 = wy * 32 + (lane >> 2);

    uint32_t ahc[4][2][4];

    auto do_chunk = [&](int c, int slot) {
        const int kc = c >> 5;
        const int d  = c & 31;
        if (d == 0) {
            #pragma unroll
            for (int ks = 0; ks < 4; ++ks)
                #pragma unroll
                for (int mt = 0; mt < 2; ++mt) {
                    const uint32_t off = (rowSel + (uint32_t)(mt * 16)) * A_STR
                                       + (uint32_t)(kc * 64 + ks * 16 + kSel) * 2u;
                    ldsm_x4(ahc[ks][mt][0], ahc[ks][mt][1],
                            ahc[ks][mt][2], ahc[ks][mt][3], sb + off);
                }
        }
        const uint32_t bbase = sb + OFF_B2 + (uint32_t)slot * BSLOT;
        float part[2][2][4];
        #pragma unroll
        for (int mt = 0; mt < 2; ++mt)
            #pragma unroll
            for (int ng = 0; ng < 2; ++ng)
                #pragma unroll
                for (int e = 0; e < 4; ++e) part[mt][ng][e] = 0.f;
        #pragma unroll
        for (int ks = 0; ks < 4; ++ks) {
            const uint32_t boff = ((uint32_t)(ks * 16) + bRow) * TSTR + bColOff;
            uint32_t b0, b1, b2, b3;
            ldsm_x4t(b0, b1, b2, b3, bbase + boff);
            #pragma unroll
            for (int mt = 0; mt < 2; ++mt) {
                mma_fp16(part[mt][0], ahc[ks][mt], b0, b1);
                mma_fp16(part[mt][1], ahc[ks][mt], b2, b3);
            }
        }
        #pragma unroll
        for (int mt = 0; mt < 2; ++mt) {
            const float s0 = sT[d * 128 + rl0 + mt * 16];
            const float s1 = sT[d * 128 + rl0 + mt * 16 + 8];
            #pragma unroll
            for (int ng = 0; ng < 2; ++ng) {
                fin[mt][ng][0] += s0 * part[mt][ng][0];
                fin[mt][ng][1] += s0 * part[mt][ng][1];
                fin[mt][ng][2] += s1 * part[mt][ng][2];
                fin[mt][ng][3] += s1 * part[mt][ng][3];
            }
        }
    };

    // 32 trips of 3 chunks; slots hold trips p-1..p+2 at iteration start.
    for (int p = 0; p < 32; ++p) {
        CP_WAIT2();              // trip p landed (trips p+1, p+2 may fly)
        __syncthreads();         // trip p-1 consumed by all; safe to refill
        if (p + 3 < 32) {
            const int c0 = 3 * (p + 3);
            load_chunk(c0,     c0 % 12);
            load_chunk(c0 + 1, (c0 + 1) % 12);
            load_chunk(c0 + 2, (c0 + 2) % 12);
        }
        CP_COMMIT();             // unconditional: keep group count aligned
        const int cb = 3 * p;
        do_chunk(cb,     cb % 12);
        do_chunk(cb + 1, (cb + 1) % 12);
        do_chunk(cb + 2, (cb + 2) % 12);
    }

    // ---- Bias chunk c=96 (K=32, A cols 192..223), slot 12, unscaled ----
    {
        const uint32_t bbase = sb + OFF_B2 + 12u * BSLOT;
        #pragma unroll
        for (int ks = 0; ks < 2; ++ks) {
            uint32_t ah[2][4];
            #pragma unroll
            for (int mt = 0; mt < 2; ++mt) {
                const uint32_t off = (rowSel + (uint32_t)(mt * 16)) * A_STR
                                   + (uint32_t)(192 + ks * 16 + kSel) * 2u;
                ldsm_x4(ah[mt][0], ah[mt][1], ah[mt][2], ah[mt][3], sb + off);
            }
            const uint32_t boff = ((uint32_t)(ks * 16) + bRow) * TSTR + bColOff;
            uint32_t b0, b1, b2, b3;
            ldsm_x4t(b0, b1, b2, b3, bbase + boff);
            #pragma unroll
            for (int mt = 0; mt < 2; ++mt) {
                mma_fp16(fin[mt][0], ah[mt], b0, b1);
                mma_fp16(fin[mt][1], ah[mt], b2, b3);
            }
        }
    }

    // Epilogue
    const int r0   = nBase + rl0;
    const int col0 = wx * 16 + 2 * (lane & 3);
    float* ob = out + (size_t)b * NN * DOUT_;
    #pragma unroll
    for (int mt = 0; mt < 2; ++mt) {
        #pragma unroll
        for (int ng = 0; ng < 2; ++ng) {
            const int row = r0 + mt * 16;
            const int cc  = col0 + ng * 8;
            *reinterpret_cast<float2*>(ob + (size_t)row * DOUT_ + cc) =
                make_float2(fin[mt][ng][0], fin[mt][ng][1]);
            *reinterpret_cast<float2*>(ob + (size_t)(row + 8) * DOUT_ + cc) =
                make_float2(fin[mt][ng][2], fin[mt][ng][3]);
        }
    }
}

// ===========================================================================
// Launch. Inputs: x, STE, R, SC, weights_pool, bias_pool.
// ===========================================================================
extern "C" void kernel_launch(void* const* d_in, const int* in_sizes, int n_in,
                              void* d_out, int out_size)
{
    (void)in_sizes; (void)n_in; (void)out_size;
    const float* x     = (const float*)d_in[0];
    const float* STE   = (const float*)d_in[1];
    const float* R     = (const float*)d_in[2];
    const float* SC    = (const float*)d_in[3];
    const float* Wp    = (const float*)d_in[4];
    const float* biasp = (const float*)d_in[5];
    float* out = (float*)d_out;

    cudaFuncSetAttribute(prop_mma<0>, cudaFuncAttributeMaxDynamicSharedMemorySize, P_SMEM);
    cudaFuncSetAttribute(prop_mma<1>, cudaFuncAttributeMaxDynamicSharedMemorySize, P_SMEM);
    cudaFuncSetAttribute(fused_mma,   cudaFuncAttributeMaxDynamicSharedMemorySize, F_SMEM);

    prop_mma<0><<<dim3(NN / 128, NB, 2), 256, P_SMEM>>>(R, SC, x, Wp, biasp);
    prop_mma<1><<<dim3(NN / 128, NB, 1), 256, P_SMEM>>>(R, SC, x, Wp, biasp);
    fused_mma<<<dim3(NN / 128, NB), 512, F_SMEM>>>(STE, out);
}